// round 11
// baseline (speedup 1.0000x reference)
#include <cuda_runtime.h>
#include <cuda_fp16.h>

#define BSZ 32
#define TT 512
#define DD 128
#define MM 50
#define NUMC 4096
#define AWC (NUMC + DD)
#define G4 512
#define RR (BSZ * TT)

// ---------------- scratch (static device arrays; no allocation) ----------------
__device__ float g_k[RR * DD];
__device__ float g_yq[RR * DD];
__device__ float g_w[RR * MM];
__device__ unsigned long long g_pack[RR * 2];
__device__ int g_prev[RR];
__device__ int g_match[RR];
__device__ float g_f[RR * DD];
__device__ float g_gi[RR * G4];
__device__ float g_H[RR * DD];
__device__ float g_C[RR * DD];

__device__ __forceinline__ float warp_sum(float v) {
#pragma unroll
    for (int o = 16; o; o >>= 1) v += __shfl_xor_sync(0xffffffffu, v, o);
    return v;
}

__device__ __forceinline__ half2 as_h2(unsigned u) { return *reinterpret_cast<half2*>(&u); }
__device__ __forceinline__ float sigf(float x) { return 1.f / (1.f + __expf(-x)); }
__device__ __forceinline__ float h2sumf(half2 v) {
    const float2 e = __half22float2(v);
    return e.x + e.y;
}
__device__ __forceinline__ float ftanh(float x) {
    float y;
    asm("tanh.approx.f32 %0, %1;" : "=f"(y) : "f"(x));
    return y;
}

// ---------------- Kernel A: gather + logits + softmax + quantize/pack ----------
__global__ __launch_bounds__(256) void kA(const int* __restrict__ q,
                                          const int* __restrict__ r,
                                          const float* __restrict__ k_emb,
                                          const float* __restrict__ Mk,
                                          const float* __restrict__ aW) {
    __shared__ float sMk[MM * DD];
    __shared__ float sk[DD];
    __shared__ float slog[MM];
    const int tid = threadIdx.x;
    for (int i = tid; i < MM * DD; i += 256) sMk[i] = Mk[i];
    const int base = blockIdx.x * 64;
    const int warp = tid >> 5, lane = tid & 31;

    for (int p = 0; p < 64; p++) {
        const int idx = base + p;
        __syncthreads();
        if (tid < DD) {
            const int qv = q[idx];
            const float kv = k_emb[qv * DD + tid];
            sk[tid] = kv;
            g_k[idx * DD + tid] = kv;
            g_yq[idx * DD + tid] = aW[tid * AWC + qv] * (float)r[idx];
        }
        __syncthreads();
        for (int m = warp; m < MM; m += 8) {
            float s = 0.f;
#pragma unroll
            for (int c = 0; c < 4; c++) s = fmaf(sk[c * 32 + lane], sMk[m * DD + c * 32 + lane], s);
            s = warp_sum(s);
            if (lane == 0) slog[m] = s;
        }
        __syncthreads();
        if (warp == 0) {
            float l0 = (lane < MM) ? slog[lane] : -1e30f;
            float l1 = (lane + 32 < MM) ? slog[lane + 32] : -1e30f;
            float mx = fmaxf(l0, l1);
#pragma unroll
            for (int o = 16; o; o >>= 1) mx = fmaxf(mx, __shfl_xor_sync(0xffffffffu, mx, o));
            float e0 = (lane < MM) ? expf(l0 - mx) : 0.f;
            float e1 = (lane + 32 < MM) ? expf(l1 - mx) : 0.f;
            float ssum = warp_sum(e0 + e1);
            float w0 = e0 / ssum, w1 = e1 / ssum;
            if (lane < MM) g_w[idx * MM + lane] = w0;
            if (lane + 32 < MM) g_w[idx * MM + lane + 32] = w1;
            const float ta = 0.075f;
            const float dba = (float)(0.088 - 0.075);
            const float dcb = (float)(1.0 - 0.088);
            float tw0 = fmaxf(fminf((w0 - ta) / dba, (1.0f - w0) / dcb), 0.f);
            float tw1 = fmaxf(fminf((w1 - ta) / dba, (1.0f - w1) / dcb), 0.f);
            int c0 = (lane < MM) ? (tw0 >= 0.6f ? 2 : (tw0 >= 0.1f ? 1 : 0)) : 0;
            int c1 = (lane + 32 < MM) ? (tw1 >= 0.6f ? 2 : (tw1 >= 0.1f ? 1 : 0)) : 0;
            unsigned b00 = __ballot_sync(0xffffffffu, c0 & 1);
            unsigned b01 = __ballot_sync(0xffffffffu, c0 >> 1);
            unsigned b10 = __ballot_sync(0xffffffffu, c1 & 1);
            unsigned b11 = __ballot_sync(0xffffffffu, c1 >> 1);
            if (lane == 0) {
                g_pack[idx * 2 + 0] = (unsigned long long)b00 | ((unsigned long long)b01 << 32);
                g_pack[idx * 2 + 1] = (unsigned long long)b10 | ((unsigned long long)b11 << 32);
            }
        }
    }
}

// ---------------- Kernel B: matched/prev via warp ballot backward scan ---------
__global__ __launch_bounds__(256) void kB() {
    const int gw = blockIdx.x * 8 + (threadIdx.x >> 5);
    const int lane = threadIdx.x & 31;
    const int b = gw / TT, i = gw % TT;
    const unsigned long long m0 = g_pack[gw * 2], m1 = g_pack[gw * 2 + 1];
    const unsigned long long* rp = &g_pack[(size_t)b * TT * 2];
    int prev = 0, matched = 0;
    for (int base = i - 1; base >= 0; base -= 32) {
        const int j = base - lane;
        const bool eq = (j >= 0) && (rp[j * 2] == m0) && (rp[j * 2 + 1] == m1);
        const unsigned msk = __ballot_sync(0xffffffffu, eq);
        if (msk) { matched = 1; prev = base - (__ffs(msk) - 1); break; }
    }
    if (lane == 0) { g_prev[gw] = prev; g_match[gw] = matched; }
}

// ---------------- Kernel C: memory-network scan -------------------------------
// 512 threads: o = tid>>2 (output elem), p = tid&3 (batch of four). 4 barriers/step.
// smem: fS 0..65536 | aS ..98304 | eS ..131072 | adS ..163840
//       xh4[4][33] @163840 | fh4[4][17] @+2112 | yh4[4][17] @+3200 | wbuf[2][4][56]f @+4288
#define C_SMEM (163840 + 4288 + 1792)
__global__ __launch_bounds__(512) void kC(const float* __restrict__ fW,
                                          const float* __restrict__ fb,
                                          const float* __restrict__ aW,
                                          const float* __restrict__ ab,
                                          const float* __restrict__ eW,
                                          const float* __restrict__ eb,
                                          const float* __restrict__ addW,
                                          const float* __restrict__ addb,
                                          const float* __restrict__ Mv0) {
    extern __shared__ char sm[];
    uint4* fS = (uint4*)sm;                        // [32][128]
    uint4* aS = (uint4*)(sm + 65536);              // [16][128]
    uint4* eS = (uint4*)(sm + 98304);              // [16][128]
    uint4* adS = (uint4*)(sm + 131072);            // [16][128]
    uint4* xh4 = (uint4*)(sm + 163840);            // [4][33]
    uint4* fh4 = (uint4*)(sm + 163840 + 2112);     // [4][17]
    uint4* yh4 = (uint4*)(sm + 163840 + 3200);     // [4][17]
    float* wbuf = (float*)(sm + 163840 + 4288);    // [2 par][4 p][56]
    half2* xh2 = (half2*)xh4;
    half2* fh2 = (half2*)fh4;
    half2* yh2 = (half2*)yh4;

    const int tid = threadIdx.x;
    const int o = tid >> 2, p = tid & 3;
    const int b0 = blockIdx.x * 4;
    const half2 z = __float2half2_rn(0.f);

    for (int i = tid; i < 128 * 128; i += 512) {
        const int jp = i >> 7, oo = i & 127;
        ((half2*)fS)[(((jp >> 2) * 128 + oo) << 2) + (jp & 3)] =
            __floats2half2_rn(fW[oo * 256 + 2 * jp], fW[oo * 256 + 2 * jp + 1]);
    }
    for (int i = tid; i < 64 * 128; i += 512) {
        const int jp = i >> 7, oo = i & 127;
        const int d = (((jp >> 2) * 128 + oo) << 2) + (jp & 3);
        ((half2*)aS)[d] =
            __floats2half2_rn(aW[oo * AWC + NUMC + 2 * jp], aW[oo * AWC + NUMC + 2 * jp + 1]);
        ((half2*)eS)[d] = __floats2half2_rn(eW[oo * 128 + 2 * jp], eW[oo * 128 + 2 * jp + 1]);
        ((half2*)adS)[d] = __floats2half2_rn(addW[oo * 128 + 2 * jp], addW[oo * 128 + 2 * jp + 1]);
    }
    // zero the 50..55 padding of all eight wbuf slots (stays zero forever)
    if (tid < 48) {
        const int slot = tid / 6, kk = tid % 6;
        wbuf[(slot >> 2) * 224 + (slot & 3) * 56 + 50 + kk] = 0.f;
    }
    const float bfv = fb[o], bav = ab[o], bev = eb[o], badv = addb[o];
    float Mv[56];
#pragma unroll
    for (int m = 0; m < MM; m++) Mv[m] = Mv0[m * DD + o];
#pragma unroll
    for (int m = MM; m < 56; m++) Mv[m] = 0.f;
    __syncthreads();

    const int xbase = p * 132;   // half2 base (33 uint4 * 4 per batch)
    const int fbase = p * 68;    // half2 base (17 uint4 * 4 per batch)
    const int x4 = p * 33, f4 = p * 17;
    const int sb = tid >> 7, sl = tid & 127;  // w-staging role

    for (int t = 0; t < TT; t++) {
        const int idxp = (b0 + p) * TT + t;
        const int par = (t & 1) * 224;
        // stage w (each 128-thread group stages its batch) and k (own batch)
        if (sl < MM) wbuf[par + sb * 56 + sl] = g_w[(size_t)((b0 + sb) * TT + t) * MM + sl];
        {
            const float kv = g_k[(size_t)idxp * DD + o];
            const float kn = __shfl_xor_sync(0xffffffffu, kv, 4);
            if (!(tid & 4)) xh2[xbase + 64 + (o >> 1)] = __floats2half2_rn(kv, kn);
        }
        const float yqv = g_yq[(size_t)idxp * DD + o];
        __syncthreads();  // B1

        // phase 1: read = w . Mv (float4 LDS, 4 accumulators)
        const float4* w4 = (const float4*)&wbuf[par + p * 56];
        float r0 = 0.f, r1 = 0.f, r2 = 0.f, r3 = 0.f;
#pragma unroll
        for (int c = 0; c < 14; c++) {
            const float4 wv = w4[c];
            r0 = fmaf(wv.x, Mv[4 * c], r0);
            r1 = fmaf(wv.y, Mv[4 * c + 1], r1);
            r2 = fmaf(wv.z, Mv[4 * c + 2], r2);
            r3 = fmaf(wv.w, Mv[4 * c + 3], r3);
        }
        {
            const float rv = (r0 + r1) + (r2 + r3);
            const float rn = __shfl_xor_sync(0xffffffffu, rv, 4);
            if (!(tid & 4)) xh2[xbase + (o >> 1)] = __floats2half2_rn(rv, rn);
        }
        __syncthreads();  // B2

        // phase 2: f = tanh([read,k] @ fW.T + fb)
        half2 F[8] = {z, z, z, z, z, z, z, z};
#pragma unroll
        for (int j = 0; j < 32; j++) {
            const uint4 wv = fS[j * 128 + o];
            const uint4 xv = xh4[x4 + j];
            const int q4 = (j & 1) << 2;
            F[q4 + 0] = __hfma2(as_h2(wv.x), as_h2(xv.x), F[q4 + 0]);
            F[q4 + 1] = __hfma2(as_h2(wv.y), as_h2(xv.y), F[q4 + 1]);
            F[q4 + 2] = __hfma2(as_h2(wv.z), as_h2(xv.z), F[q4 + 2]);
            F[q4 + 3] = __hfma2(as_h2(wv.w), as_h2(xv.w), F[q4 + 3]);
        }
        float sf = bfv;
#pragma unroll
        for (int qq = 0; qq < 8; qq++) sf += h2sumf(F[qq]);
        const float fv = ftanh(sf);
        g_f[(size_t)idxp * DD + o] = fv;
        {
            const float fn = __shfl_xor_sync(0xffffffffu, fv, 4);
            if (!(tid & 4)) fh2[fbase + (o >> 1)] = __floats2half2_rn(fv, fn);
        }
        __syncthreads();  // B3

        // phase 3: y = yq + f @ aWf.T + ab
        half2 Y[4] = {z, z, z, z};
#pragma unroll
        for (int j = 0; j < 16; j++) {
            const uint4 wv = aS[j * 128 + o];
            const uint4 xv = fh4[f4 + j];
            Y[0] = __hfma2(as_h2(wv.x), as_h2(xv.x), Y[0]);
            Y[1] = __hfma2(as_h2(wv.y), as_h2(xv.y), Y[1]);
            Y[2] = __hfma2(as_h2(wv.z), as_h2(xv.z), Y[2]);
            Y[3] = __hfma2(as_h2(wv.w), as_h2(xv.w), Y[3]);
        }
        float yv = bav + yqv;
#pragma unroll
        for (int qq = 0; qq < 4; qq++) yv += h2sumf(Y[qq]);
        {
            const float yn = __shfl_xor_sync(0xffffffffu, yv, 4);
            if (!(tid & 4)) yh2[fbase + (o >> 1)] = __floats2half2_rn(yv, yn);
        }
        __syncthreads();  // B4

        // phase 4: e = sigmoid(y@eW.T+eb), a = tanh(y@addW.T+addb)
        half2 E[4] = {z, z, z, z}, Dg[4] = {z, z, z, z};
#pragma unroll
        for (int j = 0; j < 16; j++) {
            const uint4 we = eS[j * 128 + o];
            const uint4 wa = adS[j * 128 + o];
            const uint4 xv = yh4[f4 + j];
            E[0] = __hfma2(as_h2(we.x), as_h2(xv.x), E[0]);
            E[1] = __hfma2(as_h2(we.y), as_h2(xv.y), E[1]);
            E[2] = __hfma2(as_h2(we.z), as_h2(xv.z), E[2]);
            E[3] = __hfma2(as_h2(we.w), as_h2(xv.w), E[3]);
            Dg[0] = __hfma2(as_h2(wa.x), as_h2(xv.x), Dg[0]);
            Dg[1] = __hfma2(as_h2(wa.y), as_h2(xv.y), Dg[1]);
            Dg[2] = __hfma2(as_h2(wa.z), as_h2(xv.z), Dg[2]);
            Dg[3] = __hfma2(as_h2(wa.w), as_h2(xv.w), Dg[3]);
        }
        float se = bev, sd = badv;
#pragma unroll
        for (int qq = 0; qq < 4; qq++) {
            se += h2sumf(E[qq]);
            sd += h2sumf(Dg[qq]);
        }
        const float ev = sigf(se), av = ftanh(sd);
        // phase 5: Mv update (float4 weight reads; pad weights are 0)
#pragma unroll
        for (int c = 0; c < 14; c++) {
            const float4 wv = w4[c];
            Mv[4 * c] = fmaf(wv.x, fmaf(-ev, Mv[4 * c], av), Mv[4 * c]);
            Mv[4 * c + 1] = fmaf(wv.y, fmaf(-ev, Mv[4 * c + 1], av), Mv[4 * c + 1]);
            Mv[4 * c + 2] = fmaf(wv.z, fmaf(-ev, Mv[4 * c + 2], av), Mv[4 * c + 2]);
            Mv[4 * c + 3] = fmaf(wv.w, fmaf(-ev, Mv[4 * c + 3], av), Mv[4 * c + 3]);
        }
    }
}

// ---------------- Kernel D: gi = f_all @ Wih.T + (bih + bhh) -------------------
__global__ __launch_bounds__(256) void kD(const float* __restrict__ Wih,
                                          const float* __restrict__ bih,
                                          const float* __restrict__ bhh) {
    __shared__ float sA[64][68];
    __shared__ float sB[64][68];
    const int tid = threadIdx.x;
    const int row0 = blockIdx.x * 64;
    const int n0 = blockIdx.y * 64;
    const int tx = tid & 15, ty = tid >> 4;
    float acc[4][4];
#pragma unroll
    for (int i = 0; i < 4; i++)
#pragma unroll
        for (int j = 0; j < 4; j++) acc[i][j] = 0.f;

    for (int kk = 0; kk < 128; kk += 64) {
        __syncthreads();
#pragma unroll
        for (int l = 0; l < 4; l++) {
            const int li = tid + l * 256;
            const int m = li >> 4;
            const int kq = li & 15;
            float4 v = *(const float4*)&g_f[(size_t)(row0 + m) * DD + kk + kq * 4];
            sA[kq * 4 + 0][m] = v.x; sA[kq * 4 + 1][m] = v.y;
            sA[kq * 4 + 2][m] = v.z; sA[kq * 4 + 3][m] = v.w;
            float4 u = *(const float4*)&Wih[(size_t)(n0 + m) * DD + kk + kq * 4];
            sB[kq * 4 + 0][m] = u.x; sB[kq * 4 + 1][m] = u.y;
            sB[kq * 4 + 2][m] = u.z; sB[kq * 4 + 3][m] = u.w;
        }
        __syncthreads();
#pragma unroll 8
        for (int k = 0; k < 64; k++) {
            float4 a4 = *(const float4*)&sA[k][ty * 4];
            float4 b4 = *(const float4*)&sB[k][tx * 4];
            acc[0][0] += a4.x * b4.x; acc[0][1] += a4.x * b4.y;
            acc[0][2] += a4.x * b4.z; acc[0][3] += a4.x * b4.w;
            acc[1][0] += a4.y * b4.x; acc[1][1] += a4.y * b4.y;
            acc[1][2] += a4.y * b4.z; acc[1][3] += a4.y * b4.w;
            acc[2][0] += a4.z * b4.x; acc[2][1] += a4.z * b4.y;
            acc[2][2] += a4.z * b4.z; acc[2][3] += a4.z * b4.w;
            acc[3][0] += a4.w * b4.x; acc[3][1] += a4.w * b4.y;
            acc[3][2] += a4.w * b4.z; acc[3][3] += a4.w * b4.w;
        }
    }
#pragma unroll
    for (int i = 0; i < 4; i++) {
        const int rrow = row0 + ty * 4 + i;
#pragma unroll
        for (int j = 0; j < 4; j++) {
            const int n = n0 + tx * 4 + j;
            g_gi[(size_t)rrow * G4 + n] = acc[i][j] + bih[n] + bhh[n];
        }
    }
}

// ---------------- Kernel E: LSTM scan ------------------------------------------
// 512 threads: d = tid>>2 (output dim), p = tid&3 (batch of four).
#define E_SMEM (131072 + 1088)
__global__ __launch_bounds__(512) void kE(const float* __restrict__ Whh) {
    extern __shared__ char sm2[];
    uint4* wS = (uint4*)sm2;                     // [16][512]
    uint4* hh4 = (uint4*)(sm2 + 131072);         // [4][17]
    half2* hh2 = (half2*)hh4;
    const int tid = threadIdx.x;
    const int d = tid >> 2, p = tid & 3;
    const int b0 = blockIdx.x * 4;
    const half2 z = __float2half2_rn(0.f);

    for (int i = tid; i < 64 * G4; i += 512) {
        const int jp = i >> 9, g = i & 511;
        ((half2*)wS)[(((jp >> 2) * G4 + g) << 2) + (jp & 3)] =
            __floats2half2_rn(Whh[g * DD + 2 * jp], Whh[g * DD + 2 * jp + 1]);
    }
    float h = 0.f, c = 0.f;
    __syncthreads();

    const int hbase = p * 68;  // half2 base
    const int h4 = p * 17;
    const int bB = b0 + p;

    for (int t = 0; t < TT; t++) {
        const int idxp = bB * TT + t;
        float cin;
        {
            float hv;
            if (g_match[idxp]) {
                const int pv = g_prev[idxp];
                hv = g_H[(size_t)(bB * TT + pv) * DD + d];
                cin = g_C[(size_t)(bB * TT + pv) * DD + d];
            } else {
                hv = h; cin = c;
            }
            const float hn = __shfl_xor_sync(0xffffffffu, hv, 4);
            if (!(tid & 4)) hh2[hbase + (d >> 1)] = __floats2half2_rn(hv, hn);
        }
        float gI = g_gi[(size_t)idxp * G4 + d];
        float gF = g_gi[(size_t)idxp * G4 + 128 + d];
        float gG = g_gi[(size_t)idxp * G4 + 256 + d];
        float gO = g_gi[(size_t)idxp * G4 + 384 + d];
        __syncthreads();  // A

        half2 ai[2] = {z, z}, af[2] = {z, z}, ag[2] = {z, z}, ao[2] = {z, z};
#pragma unroll
        for (int j = 0; j < 16; j++) {
            const uint4 xv = hh4[h4 + j];
            const uint4 wi = wS[j * G4 + d];
            const uint4 wf = wS[j * G4 + 128 + d];
            const uint4 wg = wS[j * G4 + 256 + d];
            const uint4 wo = wS[j * G4 + 384 + d];
            const int q = j & 1;
            ai[q] = __hfma2(as_h2(wi.x), as_h2(xv.x), ai[q]);
            ai[q] = __hfma2(as_h2(wi.y), as_h2(xv.y), ai[q]);
            ai[q] = __hfma2(as_h2(wi.z), as_h2(xv.z), ai[q]);
            ai[q] = __hfma2(as_h2(wi.w), as_h2(xv.w), ai[q]);
            af[q] = __hfma2(as_h2(wf.x), as_h2(xv.x), af[q]);
            af[q] = __hfma2(as_h2(wf.y), as_h2(xv.y), af[q]);
            af[q] = __hfma2(as_h2(wf.z), as_h2(xv.z), af[q]);
            af[q] = __hfma2(as_h2(wf.w), as_h2(xv.w), af[q]);
            ag[q] = __hfma2(as_h2(wg.x), as_h2(xv.x), ag[q]);
            ag[q] = __hfma2(as_h2(wg.y), as_h2(xv.y), ag[q]);
            ag[q] = __hfma2(as_h2(wg.z), as_h2(xv.z), ag[q]);
            ag[q] = __hfma2(as_h2(wg.w), as_h2(xv.w), ag[q]);
            ao[q] = __hfma2(as_h2(wo.x), as_h2(xv.x), ao[q]);
            ao[q] = __hfma2(as_h2(wo.y), as_h2(xv.y), ao[q]);
            ao[q] = __hfma2(as_h2(wo.z), as_h2(xv.z), ao[q]);
            ao[q] = __hfma2(as_h2(wo.w), as_h2(xv.w), ao[q]);
        }
        gI += h2sumf(ai[0]) + h2sumf(ai[1]);
        gF += h2sumf(af[0]) + h2sumf(af[1]);
        gG += h2sumf(ag[0]) + h2sumf(ag[1]);
        gO += h2sumf(ao[0]) + h2sumf(ao[1]);
        c = sigf(gF) * cin + sigf(gI) * ftanh(gG);
        h = sigf(gO) * ftanh(c);
        g_H[(size_t)idxp * DD + d] = h;
        g_C[(size_t)idxp * DD + d] = c;
        __syncthreads();  // B (protects hh staging reuse next step)
    }
}

// ---------------- Kernel F: out = sigmoid(H . pW + pb) -------------------------
__global__ __launch_bounds__(256) void kF(const float* __restrict__ pW,
                                          const float* __restrict__ pb,
                                          float* __restrict__ out) {
    const int gw = blockIdx.x * 8 + (threadIdx.x >> 5);
    const int lane = threadIdx.x & 31;
    const float4 hv = ((const float4*)(g_H + (size_t)gw * DD))[lane];
    const float4 pv = ((const float4*)pW)[lane];
    float v = hv.x * pv.x + hv.y * pv.y + hv.z * pv.z + hv.w * pv.w;
    v = warp_sum(v);
    if (lane == 0) out[gw] = sigf(v + pb[0]);
}

// ---------------- launch ----------------
extern "C" void kernel_launch(void* const* d_in, const int* in_sizes, int n_in,
                              void* d_out, int out_size) {
    const int* q = (const int*)d_in[0];
    const int* r = (const int*)d_in[1];
    const float* k_emb = (const float*)d_in[2];
    const float* Mk = (const float*)d_in[3];
    const float* Mv0 = (const float*)d_in[4];
    const float* fW = (const float*)d_in[5];
    const float* fb = (const float*)d_in[6];
    const float* aW = (const float*)d_in[7];
    const float* ab = (const float*)d_in[8];
    const float* eW = (const float*)d_in[9];
    const float* eb = (const float*)d_in[10];
    const float* addW = (const float*)d_in[11];
    const float* addb = (const float*)d_in[12];
    const float* Wih = (const float*)d_in[13];
    const float* Whh = (const float*)d_in[14];
    const float* bih = (const float*)d_in[15];
    const float* bhh = (const float*)d_in[16];
    const float* pW = (const float*)d_in[17];
    const float* pb = (const float*)d_in[18];
    float* out = (float*)d_out;

    cudaFuncSetAttribute(kC, cudaFuncAttributeMaxDynamicSharedMemorySize, C_SMEM);
    cudaFuncSetAttribute(kE, cudaFuncAttributeMaxDynamicSharedMemorySize, E_SMEM);

    kA<<<256, 256>>>(q, r, k_emb, Mk, aW);
    kB<<<RR / 8, 256>>>();
    kC<<<BSZ / 4, 512, C_SMEM>>>(fW, fb, aW, ab, eW, eb, addW, addb, Mv0);
    kD<<<dim3(RR / 64, G4 / 64), 256>>>(Wih, bih, bhh);
    kE<<<BSZ / 4, 512, E_SMEM>>>(Whh);
    kF<<<RR / 8, 256>>>(pW, pb, out);
}

// round 12
// speedup vs baseline: 1.5700x; 1.5700x over previous
#include <cuda_runtime.h>
#include <cuda_fp16.h>

#define BSZ 32
#define TT 512
#define DD 128
#define MM 50
#define NUMC 4096
#define AWC (NUMC + DD)
#define G4 512
#define RR (BSZ * TT)

// ---------------- scratch (static device arrays; no allocation) ----------------
__device__ float g_w[RR * MM];
__device__ unsigned long long g_pack[RR * 2];
__device__ int g_prev[RR];
__device__ int g_match[RR];
__device__ float g_f[RR * DD];
__device__ float g_gi[RR * G4];
__device__ float g_H[RR * DD];
__device__ float g_C[RR * DD];
// fused-weight precompute + per-step streamed gathers
__device__ float g_We[DD * DD];
__device__ float g_Wa[DD * DD];
__device__ float g_ce[DD];
__device__ float g_ca[DD];
__device__ float g_Ae[NUMC * DD];
__device__ float g_Aa[NUMC * DD];
__device__ float g_KF[NUMC * DD];
__device__ float g_KFg[RR * DD];
__device__ float g_Aeg[RR * DD];
__device__ float g_Aag[RR * DD];

__device__ __forceinline__ float warp_sum(float v) {
#pragma unroll
    for (int o = 16; o; o >>= 1) v += __shfl_xor_sync(0xffffffffu, v, o);
    return v;
}
__device__ __forceinline__ half2 as_h2(unsigned u) { return *reinterpret_cast<half2*>(&u); }
__device__ __forceinline__ float sigf(float x) { return 1.f / (1.f + __expf(-x)); }
__device__ __forceinline__ float h2sumf(half2 v) {
    const float2 e = __half22float2(v);
    return e.x + e.y;
}
__device__ __forceinline__ float ftanh(float x) {
    float y;
    asm("tanh.approx.f32 %0, %1;" : "=f"(y) : "f"(x));
    return y;
}

// ---------------- kP0: We/Wa (128x128) + ce/ca ---------------------------------
__global__ __launch_bounds__(128) void kP0(const float* __restrict__ aW,
                                           const float* __restrict__ eW,
                                           const float* __restrict__ addW,
                                           const float* __restrict__ ab,
                                           const float* __restrict__ eb,
                                           const float* __restrict__ addb) {
    const int o = blockIdx.x, j = threadIdx.x;
    float se = 0.f, sa = 0.f;
#pragma unroll 4
    for (int d = 0; d < DD; d++) {
        const float av = aW[d * AWC + NUMC + j];
        se = fmaf(av, eW[o * DD + d], se);
        sa = fmaf(av, addW[o * DD + d], sa);
    }
    g_We[o * DD + j] = se;
    g_Wa[o * DD + j] = sa;
    if (j == 0) {
        float ce = eb[o], ca = addb[o];
        for (int d = 0; d < DD; d++) {
            ce = fmaf(ab[d], eW[o * DD + d], ce);
            ca = fmaf(ab[d], addW[o * DD + d], ca);
        }
        g_ce[o] = ce;
        g_ca[o] = ca;
    }
}

// ---------------- kP1: A_e / A_a / KF (4096x128 each) --------------------------
__global__ __launch_bounds__(128) void kP1(const float* __restrict__ aW,
                                           const float* __restrict__ eW,
                                           const float* __restrict__ addW,
                                           const float* __restrict__ k_emb,
                                           const float* __restrict__ fW,
                                           const float* __restrict__ fb) {
    __shared__ float sA[DD][33];
    const int v = blockIdx.y;
    const int qv0 = blockIdx.x * 32;
    const int tid = threadIdx.x;
    if (v < 2) {
        const float4* s4 = (const float4*)(aW + (size_t)tid * AWC + qv0);
#pragma unroll
        for (int i = 0; i < 8; i++) {
            const float4 x = s4[i];
            sA[tid][4 * i] = x.x; sA[tid][4 * i + 1] = x.y;
            sA[tid][4 * i + 2] = x.z; sA[tid][4 * i + 3] = x.w;
        }
    } else {
#pragma unroll 4
        for (int i = 0; i < 32; i++) sA[tid][i] = k_emb[(size_t)(qv0 + i) * DD + tid];
    }
    __syncthreads();
    const int o = tid;
    const float* Brow = (v == 0) ? (eW + o * DD) : (v == 1) ? (addW + o * DD) : (fW + o * 256 + 128);
    const float bias = (v == 2) ? fb[o] : 0.f;
    float* dst = (v == 0) ? g_Ae : (v == 1) ? g_Aa : g_KF;
    for (int qv = 0; qv < 32; qv++) {
        float s0 = bias, s1 = 0.f;
#pragma unroll 8
        for (int d = 0; d < DD; d += 2) {
            s0 = fmaf(sA[d][qv], __ldg(&Brow[d]), s0);
            s1 = fmaf(sA[d + 1][qv], __ldg(&Brow[d + 1]), s1);
        }
        dst[(size_t)(qv0 + qv) * DD + o] = s0 + s1;
    }
}

// ---------------- Kernel A: gathers + logits + softmax + quantize/pack ---------
__global__ __launch_bounds__(256) void kA(const int* __restrict__ q,
                                          const int* __restrict__ r,
                                          const float* __restrict__ k_emb,
                                          const float* __restrict__ Mk) {
    __shared__ float sMk[MM * DD];
    __shared__ float sk[DD];
    __shared__ float slog[MM];
    const int tid = threadIdx.x;
    for (int i = tid; i < MM * DD; i += 256) sMk[i] = Mk[i];
    const int base = blockIdx.x * 64;
    const int warp = tid >> 5, lane = tid & 31;

    for (int p = 0; p < 64; p++) {
        const int idx = base + p;
        __syncthreads();
        if (tid < DD) {
            const int qv = q[idx];
            const int rv = r[idx];
            sk[tid] = k_emb[qv * DD + tid];
            g_KFg[(size_t)idx * DD + tid] = g_KF[(size_t)qv * DD + tid];
            const float ae = rv ? g_Ae[(size_t)qv * DD + tid] : 0.f;
            const float aa = rv ? g_Aa[(size_t)qv * DD + tid] : 0.f;
            g_Aeg[(size_t)idx * DD + tid] = ae + g_ce[tid];
            g_Aag[(size_t)idx * DD + tid] = aa + g_ca[tid];
        }
        __syncthreads();
        for (int m = warp; m < MM; m += 8) {
            float s = 0.f;
#pragma unroll
            for (int c = 0; c < 4; c++) s = fmaf(sk[c * 32 + lane], sMk[m * DD + c * 32 + lane], s);
            s = warp_sum(s);
            if (lane == 0) slog[m] = s;
        }
        __syncthreads();
        if (warp == 0) {
            float l0 = (lane < MM) ? slog[lane] : -1e30f;
            float l1 = (lane + 32 < MM) ? slog[lane + 32] : -1e30f;
            float mx = fmaxf(l0, l1);
#pragma unroll
            for (int o = 16; o; o >>= 1) mx = fmaxf(mx, __shfl_xor_sync(0xffffffffu, mx, o));
            float e0 = (lane < MM) ? expf(l0 - mx) : 0.f;
            float e1 = (lane + 32 < MM) ? expf(l1 - mx) : 0.f;
            float ssum = warp_sum(e0 + e1);
            float w0 = e0 / ssum, w1 = e1 / ssum;
            if (lane < MM) g_w[idx * MM + lane] = w0;
            if (lane + 32 < MM) g_w[idx * MM + lane + 32] = w1;
            const float ta = 0.075f;
            const float dba = (float)(0.088 - 0.075);
            const float dcb = (float)(1.0 - 0.088);
            float tw0 = fmaxf(fminf((w0 - ta) / dba, (1.0f - w0) / dcb), 0.f);
            float tw1 = fmaxf(fminf((w1 - ta) / dba, (1.0f - w1) / dcb), 0.f);
            int c0 = (lane < MM) ? (tw0 >= 0.6f ? 2 : (tw0 >= 0.1f ? 1 : 0)) : 0;
            int c1 = (lane + 32 < MM) ? (tw1 >= 0.6f ? 2 : (tw1 >= 0.1f ? 1 : 0)) : 0;
            unsigned b00 = __ballot_sync(0xffffffffu, c0 & 1);
            unsigned b01 = __ballot_sync(0xffffffffu, c0 >> 1);
            unsigned b10 = __ballot_sync(0xffffffffu, c1 & 1);
            unsigned b11 = __ballot_sync(0xffffffffu, c1 >> 1);
            if (lane == 0) {
                g_pack[idx * 2 + 0] = (unsigned long long)b00 | ((unsigned long long)b01 << 32);
                g_pack[idx * 2 + 1] = (unsigned long long)b10 | ((unsigned long long)b11 << 32);
            }
        }
    }
}

// ---------------- Kernel B: matched/prev via warp ballot backward scan ---------
__global__ __launch_bounds__(256) void kB() {
    const int gw = blockIdx.x * 8 + (threadIdx.x >> 5);
    const int lane = threadIdx.x & 31;
    const int b = gw / TT, i = gw % TT;
    const unsigned long long m0 = g_pack[gw * 2], m1 = g_pack[gw * 2 + 1];
    const unsigned long long* rp = &g_pack[(size_t)b * TT * 2];
    int prev = 0, matched = 0;
    for (int base = i - 1; base >= 0; base -= 32) {
        const int j = base - lane;
        const bool eq = (j >= 0) && (rp[j * 2] == m0) && (rp[j * 2 + 1] == m1);
        const unsigned msk = __ballot_sync(0xffffffffu, eq);
        if (msk) { matched = 1; prev = base - (__ffs(msk) - 1); break; }
    }
    if (lane == 0) { g_prev[gw] = prev; g_match[gw] = matched; }
}

// ---------------- Kernel C: fused memory-network scan, 2 barriers/step ---------
// 256 threads: o = tid>>1, p = tid&1 (batch of the pair).
// smem: fS 0..32768 | eS ..65536 | adS ..98304 | xh4[2][17] | fh4[2][17] | wbuf[2][2][56]f
#define C_SMEM (98304 + 544 + 544 + 896)
__global__ __launch_bounds__(256) void kC(const float* __restrict__ fW,
                                          const float* __restrict__ Mv0) {
    extern __shared__ char sm[];
    uint4* fS = (uint4*)sm;                       // [16][128]
    uint4* eS = (uint4*)(sm + 32768);             // [16][128]
    uint4* adS = (uint4*)(sm + 65536);            // [16][128]
    uint4* xh4 = (uint4*)(sm + 98304);            // [2][17]
    uint4* fh4 = (uint4*)(sm + 98304 + 544);      // [2][17]
    float* wbuf = (float*)(sm + 98304 + 1088);    // [2 par][2 p][56]
    half2* xh2 = (half2*)xh4;
    half2* fh2 = (half2*)fh4;

    const int tid = threadIdx.x;
    const int o = tid >> 1, p = tid & 1;
    const int b0 = blockIdx.x * 2;
    const half2 z = __float2half2_rn(0.f);

    for (int i = tid; i < 64 * 128; i += 256) {
        const int jp = i >> 7, oo = i & 127;
        const int d = (((jp >> 2) * 128 + oo) << 2) + (jp & 3);
        ((half2*)fS)[d] = __floats2half2_rn(fW[oo * 256 + 2 * jp], fW[oo * 256 + 2 * jp + 1]);
        ((half2*)eS)[d] = __floats2half2_rn(g_We[oo * 128 + 2 * jp], g_We[oo * 128 + 2 * jp + 1]);
        ((half2*)adS)[d] = __floats2half2_rn(g_Wa[oo * 128 + 2 * jp], g_Wa[oo * 128 + 2 * jp + 1]);
    }
    // zero the 50..55 padding of all four wbuf slots
    if (tid < 24) {
        const int slot = tid / 6, kk = tid % 6;
        wbuf[(slot >> 1) * 112 + (slot & 1) * 56 + 50 + kk] = 0.f;
    }
    float Mv[56];
#pragma unroll
    for (int m = 0; m < MM; m++) Mv[m] = Mv0[m * DD + o];
#pragma unroll
    for (int m = MM; m < 56; m++) Mv[m] = 0.f;
    // prologue: stage w for t=0 into parity slot 0
    if (tid < MM) wbuf[tid] = g_w[(size_t)(b0 * TT) * MM + tid];
    else if (tid >= 128 && tid < 128 + MM) wbuf[56 + tid - 128] = g_w[(size_t)((b0 + 1) * TT) * MM + tid - 128];
    __syncthreads();

    const int xbase = p * 68, x4 = p * 17;
    int idxp = (b0 + p) * TT;

    for (int t = 0; t < TT; t++, idxp++) {
        const int par = (t & 1) * 112;
        // streamed per-step gathers (independent of recurrence)
        const float kfg = g_KFg[(size_t)idxp * DD + o];
        const float geg = g_Aeg[(size_t)idxp * DD + o];
        const float gag = g_Aag[(size_t)idxp * DD + o];
        // phase 1: read = w . Mv
        const float4* w4 = (const float4*)&wbuf[par + p * 56];
        float r0 = 0.f, r1 = 0.f, r2 = 0.f, r3 = 0.f;
#pragma unroll
        for (int c = 0; c < 14; c++) {
            const float4 wv = w4[c];
            r0 = fmaf(wv.x, Mv[4 * c], r0);
            r1 = fmaf(wv.y, Mv[4 * c + 1], r1);
            r2 = fmaf(wv.z, Mv[4 * c + 2], r2);
            r3 = fmaf(wv.w, Mv[4 * c + 3], r3);
        }
        {
            const float rv = (r0 + r1) + (r2 + r3);
            const float rn = __shfl_xor_sync(0xffffffffu, rv, 2);
            if (!(tid & 2)) xh2[xbase + (o >> 1)] = __floats2half2_rn(rv, rn);
        }
        __syncthreads();  // B1

        // phase 2: f = tanh(read . fW_r^T + KF[q])
        half2 F[4] = {z, z, z, z};
#pragma unroll
        for (int j = 0; j < 16; j++) {
            const uint4 wv = fS[j * 128 + o];
            const uint4 xv = xh4[x4 + j];
            F[0] = __hfma2(as_h2(wv.x), as_h2(xv.x), F[0]);
            F[1] = __hfma2(as_h2(wv.y), as_h2(xv.y), F[1]);
            F[2] = __hfma2(as_h2(wv.z), as_h2(xv.z), F[2]);
            F[3] = __hfma2(as_h2(wv.w), as_h2(xv.w), F[3]);
        }
        float sf = kfg;
#pragma unroll
        for (int qq = 0; qq < 4; qq++) sf += h2sumf(F[qq]);
        const float fv = ftanh(sf);
        g_f[(size_t)idxp * DD + o] = fv;
        {
            const float fn = __shfl_xor_sync(0xffffffffu, fv, 2);
            if (!(tid & 2)) fh2[xbase + (o >> 1)] = __floats2half2_rn(fv, fn);
        }
        // stage w for t+1 into the other parity slot
        if (t + 1 < TT) {
            const int npar = ((t + 1) & 1) * 112;
            if (tid < MM) wbuf[npar + tid] = g_w[(size_t)(b0 * TT + t + 1) * MM + tid];
            else if (tid >= 128 && tid < 128 + MM)
                wbuf[npar + 56 + tid - 128] = g_w[(size_t)((b0 + 1) * TT + t + 1) * MM + tid - 128];
        }
        __syncthreads();  // B2

        // phase 3: e = sig(f.We + Aeg), a = tanh(f.Wa + Aag)
        half2 E[4] = {z, z, z, z}, Dg[4] = {z, z, z, z};
#pragma unroll
        for (int j = 0; j < 16; j++) {
            const uint4 we = eS[j * 128 + o];
            const uint4 wa = adS[j * 128 + o];
            const uint4 xv = fh4[x4 + j];
            E[0] = __hfma2(as_h2(we.x), as_h2(xv.x), E[0]);
            E[1] = __hfma2(as_h2(we.y), as_h2(xv.y), E[1]);
            E[2] = __hfma2(as_h2(we.z), as_h2(xv.z), E[2]);
            E[3] = __hfma2(as_h2(we.w), as_h2(xv.w), E[3]);
            Dg[0] = __hfma2(as_h2(wa.x), as_h2(xv.x), Dg[0]);
            Dg[1] = __hfma2(as_h2(wa.y), as_h2(xv.y), Dg[1]);
            Dg[2] = __hfma2(as_h2(wa.z), as_h2(xv.z), Dg[2]);
            Dg[3] = __hfma2(as_h2(wa.w), as_h2(xv.w), Dg[3]);
        }
        float se = geg, sd = gag;
#pragma unroll
        for (int qq = 0; qq < 4; qq++) {
            se += h2sumf(E[qq]);
            sd += h2sumf(Dg[qq]);
        }
        const float ev = sigf(se), av = ftanh(sd);
        // phase 4: Mv update
#pragma unroll
        for (int c = 0; c < 14; c++) {
            const float4 wv = w4[c];
            Mv[4 * c] = fmaf(wv.x, fmaf(-ev, Mv[4 * c], av), Mv[4 * c]);
            Mv[4 * c + 1] = fmaf(wv.y, fmaf(-ev, Mv[4 * c + 1], av), Mv[4 * c + 1]);
            Mv[4 * c + 2] = fmaf(wv.z, fmaf(-ev, Mv[4 * c + 2], av), Mv[4 * c + 2]);
            Mv[4 * c + 3] = fmaf(wv.w, fmaf(-ev, Mv[4 * c + 3], av), Mv[4 * c + 3]);
        }
    }
}

// ---------------- Kernel D: gi = f_all @ Wih.T + (bih + bhh) -------------------
__global__ __launch_bounds__(256) void kD(const float* __restrict__ Wih,
                                          const float* __restrict__ bih,
                                          const float* __restrict__ bhh) {
    __shared__ float sA[64][68];
    __shared__ float sB[64][68];
    const int tid = threadIdx.x;
    const int row0 = blockIdx.x * 64;
    const int n0 = blockIdx.y * 64;
    const int tx = tid & 15, ty = tid >> 4;
    float acc[4][4];
#pragma unroll
    for (int i = 0; i < 4; i++)
#pragma unroll
        for (int j = 0; j < 4; j++) acc[i][j] = 0.f;

    for (int kk = 0; kk < 128; kk += 64) {
        __syncthreads();
#pragma unroll
        for (int l = 0; l < 4; l++) {
            const int li = tid + l * 256;
            const int m = li >> 4;
            const int kq = li & 15;
            float4 v = *(const float4*)&g_f[(size_t)(row0 + m) * DD + kk + kq * 4];
            sA[kq * 4 + 0][m] = v.x; sA[kq * 4 + 1][m] = v.y;
            sA[kq * 4 + 2][m] = v.z; sA[kq * 4 + 3][m] = v.w;
            float4 u = *(const float4*)&Wih[(size_t)(n0 + m) * DD + kk + kq * 4];
            sB[kq * 4 + 0][m] = u.x; sB[kq * 4 + 1][m] = u.y;
            sB[kq * 4 + 2][m] = u.z; sB[kq * 4 + 3][m] = u.w;
        }
        __syncthreads();
#pragma unroll 8
        for (int k = 0; k < 64; k++) {
            float4 a4 = *(const float4*)&sA[k][ty * 4];
            float4 b4 = *(const float4*)&sB[k][tx * 4];
            acc[0][0] += a4.x * b4.x; acc[0][1] += a4.x * b4.y;
            acc[0][2] += a4.x * b4.z; acc[0][3] += a4.x * b4.w;
            acc[1][0] += a4.y * b4.x; acc[1][1] += a4.y * b4.y;
            acc[1][2] += a4.y * b4.z; acc[1][3] += a4.y * b4.w;
            acc[2][0] += a4.z * b4.x; acc[2][1] += a4.z * b4.y;
            acc[2][2] += a4.z * b4.z; acc[2][3] += a4.z * b4.w;
            acc[3][0] += a4.w * b4.x; acc[3][1] += a4.w * b4.y;
            acc[3][2] += a4.w * b4.z; acc[3][3] += a4.w * b4.w;
        }
    }
#pragma unroll
    for (int i = 0; i < 4; i++) {
        const int rrow = row0 + ty * 4 + i;
#pragma unroll
        for (int j = 0; j < 4; j++) {
            const int n = n0 + tx * 4 + j;
            g_gi[(size_t)rrow * G4 + n] = acc[i][j] + bih[n] + bhh[n];
        }
    }
}

// ---------------- Kernel E: LSTM scan (R10-identical) --------------------------
// 256 threads: d = tid>>1 (output dim), p = tid&1 (batch of the pair).
#define E_SMEM (131072 + 576)
__global__ __launch_bounds__(256) void kE(const float* __restrict__ Whh) {
    extern __shared__ char sm2[];
    uint4* wS = (uint4*)sm2;                     // [16][512]
    uint4* hh4 = (uint4*)(sm2 + 131072);         // [33]: A@0, B@17
    half2* hh2 = (half2*)hh4;
    const int tid = threadIdx.x;
    const int d = tid >> 1, p = tid & 1;
    const int b0 = blockIdx.x * 2;
    const half2 z = __float2half2_rn(0.f);

    for (int i = tid; i < 64 * G4; i += 256) {
        const int jp = i >> 9, g = i & 511;
        ((half2*)wS)[(((jp >> 2) * G4 + g) << 2) + (jp & 3)] =
            __floats2half2_rn(Whh[g * DD + 2 * jp], Whh[g * DD + 2 * jp + 1]);
    }
    float h = 0.f, c = 0.f;
    __syncthreads();

    const int hbase = p * 68;
    const int h4 = p * 17;
    const int bB = b0 + p;

    for (int t = 0; t < TT; t++) {
        const int idxp = bB * TT + t;
        float cin;
        {
            float hv;
            if (g_match[idxp]) {
                const int pv = g_prev[idxp];
                hv = g_H[(size_t)(bB * TT + pv) * DD + d];
                cin = g_C[(size_t)(bB * TT + pv) * DD + d];
            } else {
                hv = h; cin = c;
            }
            const float hn = __shfl_xor_sync(0xffffffffu, hv, 2);
            if (!(tid & 2)) hh2[hbase + (d >> 1)] = __floats2half2_rn(hv, hn);
        }
        float gI = g_gi[(size_t)idxp * G4 + d];
        float gF = g_gi[(size_t)idxp * G4 + 128 + d];
        float gG = g_gi[(size_t)idxp * G4 + 256 + d];
        float gO = g_gi[(size_t)idxp * G4 + 384 + d];
        __syncthreads();  // A

        half2 ai[2] = {z, z}, af[2] = {z, z}, ag[2] = {z, z}, ao[2] = {z, z};
#pragma unroll
        for (int j = 0; j < 16; j++) {
            const uint4 xv = hh4[h4 + j];
            const uint4 wi = wS[j * G4 + d];
            const uint4 wf = wS[j * G4 + 128 + d];
            const uint4 wg = wS[j * G4 + 256 + d];
            const uint4 wo = wS[j * G4 + 384 + d];
            const int q = j & 1;
            ai[q] = __hfma2(as_h2(wi.x), as_h2(xv.x), ai[q]);
            ai[q] = __hfma2(as_h2(wi.y), as_h2(xv.y), ai[q]);
            ai[q] = __hfma2(as_h2(wi.z), as_h2(xv.z), ai[q]);
            ai[q] = __hfma2(as_h2(wi.w), as_h2(xv.w), ai[q]);
            af[q] = __hfma2(as_h2(wf.x), as_h2(xv.x), af[q]);
            af[q] = __hfma2(as_h2(wf.y), as_h2(xv.y), af[q]);
            af[q] = __hfma2(as_h2(wf.z), as_h2(xv.z), af[q]);
            af[q] = __hfma2(as_h2(wf.w), as_h2(xv.w), af[q]);
            ag[q] = __hfma2(as_h2(wg.x), as_h2(xv.x), ag[q]);
            ag[q] = __hfma2(as_h2(wg.y), as_h2(xv.y), ag[q]);
            ag[q] = __hfma2(as_h2(wg.z), as_h2(xv.z), ag[q]);
            ag[q] = __hfma2(as_h2(wg.w), as_h2(xv.w), ag[q]);
            ao[q] = __hfma2(as_h2(wo.x), as_h2(xv.x), ao[q]);
            ao[q] = __hfma2(as_h2(wo.y), as_h2(xv.y), ao[q]);
            ao[q] = __hfma2(as_h2(wo.z), as_h2(xv.z), ao[q]);
            ao[q] = __hfma2(as_h2(wo.w), as_h2(xv.w), ao[q]);
        }
        gI += h2sumf(ai[0]) + h2sumf(ai[1]);
        gF += h2sumf(af[0]) + h2sumf(af[1]);
        gG += h2sumf(ag[0]) + h2sumf(ag[1]);
        gO += h2sumf(ao[0]) + h2sumf(ao[1]);
        c = sigf(gF) * cin + sigf(gI) * ftanh(gG);
        h = sigf(gO) * ftanh(c);
        g_H[(size_t)idxp * DD + d] = h;
        g_C[(size_t)idxp * DD + d] = c;
        __syncthreads();  // B
    }
}

// ---------------- Kernel F: out = sigmoid(H . pW + pb) -------------------------
__global__ __launch_bounds__(256) void kF(const float* __restrict__ pW,
                                          const float* __restrict__ pb,
                                          float* __restrict__ out) {
    const int gw = blockIdx.x * 8 + (threadIdx.x >> 5);
    const int lane = threadIdx.x & 31;
    const float4 hv = ((const float4*)(g_H + (size_t)gw * DD))[lane];
    const float4 pv = ((const float4*)pW)[lane];
    float v = hv.x * pv.x + hv.y * pv.y + hv.z * pv.z + hv.w * pv.w;
    v = warp_sum(v);
    if (lane == 0) out[gw] = sigf(v + pb[0]);
}

// ---------------- launch ----------------
extern "C" void kernel_launch(void* const* d_in, const int* in_sizes, int n_in,
                              void* d_out, int out_size) {
    const int* q = (const int*)d_in[0];
    const int* r = (const int*)d_in[1];
    const float* k_emb = (const float*)d_in[2];
    const float* Mk = (const float*)d_in[3];
    const float* Mv0 = (const float*)d_in[4];
    const float* fW = (const float*)d_in[5];
    const float* fb = (const float*)d_in[6];
    const float* aW = (const float*)d_in[7];
    const float* ab = (const float*)d_in[8];
    const float* eW = (const float*)d_in[9];
    const float* eb = (const float*)d_in[10];
    const float* addW = (const float*)d_in[11];
    const float* addb = (const float*)d_in[12];
    const float* Wih = (const float*)d_in[13];
    const float* Whh = (const float*)d_in[14];
    const float* bih = (const float*)d_in[15];
    const float* bhh = (const float*)d_in[16];
    const float* pW = (const float*)d_in[17];
    const float* pb = (const float*)d_in[18];
    float* out = (float*)d_out;

    cudaFuncSetAttribute(kC, cudaFuncAttributeMaxDynamicSharedMemorySize, C_SMEM);
    cudaFuncSetAttribute(kE, cudaFuncAttributeMaxDynamicSharedMemorySize, E_SMEM);

    kP0<<<128, 128>>>(aW, eW, addW, ab, eb, addb);
    kP1<<<dim3(128, 3), 128>>>(aW, eW, addW, k_emb, fW, fb);
    kA<<<256, 256>>>(q, r, k_emb, Mk);
    kB<<<RR / 8, 256>>>();
    kC<<<BSZ / 2, 256, C_SMEM>>>(fW, Mv0);
    kD<<<dim3(RR / 64, G4 / 64), 256>>>(Wih, bih, bhh);
    kE<<<BSZ / 2, 256, E_SMEM>>>(Whh);
    kF<<<RR / 8, 256>>>(pW, pb, out);
}

// round 13
// speedup vs baseline: 2.3934x; 1.5245x over previous
#include <cuda_runtime.h>
#include <cuda_fp16.h>

#define BSZ 32
#define TT 512
#define DD 128
#define MM 50
#define NUMC 4096
#define AWC (NUMC + DD)
#define G4 512
#define RR (BSZ * TT)
#define NPAIR 16

// ---------------- scratch (static device arrays; no allocation) ----------------
__device__ float g_k[RR * DD];
__device__ float g_yq[RR * DD];
__device__ float g_w[RR * MM];
__device__ unsigned long long g_pack[RR * 2];
__device__ int g_prev[RR];
__device__ int g_match[RR];
__device__ float g_f[RR * DD];
__device__ float g_gi[RR * G4];
__device__ float g_H[RR * DD];
__device__ float g_C[RR * DD];
__device__ int g_prog[2 * NPAIR];   // [0..15]=f progress, [16..31]=gi progress

__device__ __forceinline__ float warp_sum(float v) {
#pragma unroll
    for (int o = 16; o; o >>= 1) v += __shfl_xor_sync(0xffffffffu, v, o);
    return v;
}
__device__ __forceinline__ half2 as_h2(unsigned u) { return *reinterpret_cast<half2*>(&u); }
__device__ __forceinline__ float sigf(float x) { return 1.f / (1.f + __expf(-x)); }
__device__ __forceinline__ float h2sumf(half2 v) {
    const float2 e = __half22float2(v);
    return e.x + e.y;
}
__device__ __forceinline__ float ftanh(float x) {
    float y;
    asm("tanh.approx.f32 %0, %1;" : "=f"(y) : "f"(x));
    return y;
}
__device__ __forceinline__ void wait_ge(const int* flag, int v) {
    while (*((volatile const int*)flag) < v) __nanosleep(40);
    __threadfence();
}

// ---------------- Kernel A: gather + logits + softmax + pack + flag-zero -------
__global__ __launch_bounds__(256) void kA(const int* __restrict__ q,
                                          const int* __restrict__ r,
                                          const float* __restrict__ k_emb,
                                          const float* __restrict__ Mk,
                                          const float* __restrict__ aW) {
    __shared__ float sMk[MM * DD];
    __shared__ float sk[DD];
    __shared__ float slog[MM];
    const int tid = threadIdx.x;
    if (blockIdx.x == 0 && tid < 2 * NPAIR) g_prog[tid] = 0;
    for (int i = tid; i < MM * DD; i += 256) sMk[i] = Mk[i];
    const int base = blockIdx.x * 64;
    const int warp = tid >> 5, lane = tid & 31;

    for (int p = 0; p < 64; p++) {
        const int idx = base + p;
        __syncthreads();
        if (tid < DD) {
            const int qv = q[idx];
            const float kv = k_emb[qv * DD + tid];
            sk[tid] = kv;
            g_k[idx * DD + tid] = kv;
            g_yq[idx * DD + tid] = aW[tid * AWC + qv] * (float)r[idx];
        }
        __syncthreads();
        for (int m = warp; m < MM; m += 8) {
            float s = 0.f;
#pragma unroll
            for (int c = 0; c < 4; c++) s = fmaf(sk[c * 32 + lane], sMk[m * DD + c * 32 + lane], s);
            s = warp_sum(s);
            if (lane == 0) slog[m] = s;
        }
        __syncthreads();
        if (warp == 0) {
            float l0 = (lane < MM) ? slog[lane] : -1e30f;
            float l1 = (lane + 32 < MM) ? slog[lane + 32] : -1e30f;
            float mx = fmaxf(l0, l1);
#pragma unroll
            for (int o = 16; o; o >>= 1) mx = fmaxf(mx, __shfl_xor_sync(0xffffffffu, mx, o));
            float e0 = (lane < MM) ? expf(l0 - mx) : 0.f;
            float e1 = (lane + 32 < MM) ? expf(l1 - mx) : 0.f;
            float ssum = warp_sum(e0 + e1);
            float w0 = e0 / ssum, w1 = e1 / ssum;
            if (lane < MM) g_w[idx * MM + lane] = w0;
            if (lane + 32 < MM) g_w[idx * MM + lane + 32] = w1;
            const float ta = 0.075f;
            const float dba = (float)(0.088 - 0.075);
            const float dcb = (float)(1.0 - 0.088);
            float tw0 = fmaxf(fminf((w0 - ta) / dba, (1.0f - w0) / dcb), 0.f);
            float tw1 = fmaxf(fminf((w1 - ta) / dba, (1.0f - w1) / dcb), 0.f);
            int c0 = (lane < MM) ? (tw0 >= 0.6f ? 2 : (tw0 >= 0.1f ? 1 : 0)) : 0;
            int c1 = (lane + 32 < MM) ? (tw1 >= 0.6f ? 2 : (tw1 >= 0.1f ? 1 : 0)) : 0;
            unsigned b00 = __ballot_sync(0xffffffffu, c0 & 1);
            unsigned b01 = __ballot_sync(0xffffffffu, c0 >> 1);
            unsigned b10 = __ballot_sync(0xffffffffu, c1 & 1);
            unsigned b11 = __ballot_sync(0xffffffffu, c1 >> 1);
            if (lane == 0) {
                g_pack[idx * 2 + 0] = (unsigned long long)b00 | ((unsigned long long)b01 << 32);
                g_pack[idx * 2 + 1] = (unsigned long long)b10 | ((unsigned long long)b11 << 32);
            }
        }
    }
}

// ---------------- Kernel B: matched/prev via warp ballot backward scan ---------
__global__ __launch_bounds__(256) void kB() {
    const int gw = blockIdx.x * 8 + (threadIdx.x >> 5);
    const int lane = threadIdx.x & 31;
    const int b = gw / TT, i = gw % TT;
    const unsigned long long m0 = g_pack[gw * 2], m1 = g_pack[gw * 2 + 1];
    const unsigned long long* rp = &g_pack[(size_t)b * TT * 2];
    int prev = 0, matched = 0;
    for (int base = i - 1; base >= 0; base -= 32) {
        const int j = base - lane;
        const bool eq = (j >= 0) && (rp[j * 2] == m0) && (rp[j * 2 + 1] == m1);
        const unsigned msk = __ballot_sync(0xffffffffu, eq);
        if (msk) { matched = 1; prev = base - (__ffs(msk) - 1); break; }
    }
    if (lane == 0) { g_prev[gw] = prev; g_match[gw] = matched; }
}

// ---------------- kScan: persistent pipelined mega-kernel ----------------------
// 48 blocks x 256 threads. role = blockIdx.x>>4: 0=memnet(kC), 1=gi worker, 2=lstm(kE)
#define SC_SMEM (163840 + 2240 + 896)
__global__ __launch_bounds__(256) void kScan(const float* __restrict__ fW,
                                             const float* __restrict__ fb,
                                             const float* __restrict__ aW,
                                             const float* __restrict__ ab,
                                             const float* __restrict__ eW,
                                             const float* __restrict__ eb,
                                             const float* __restrict__ addW,
                                             const float* __restrict__ addb,
                                             const float* __restrict__ Mv0,
                                             const float* __restrict__ Wih,
                                             const float* __restrict__ bih,
                                             const float* __restrict__ bhh,
                                             const float* __restrict__ Whh) {
    extern __shared__ char sm[];
    const int tid = threadIdx.x;
    const int role = blockIdx.x >> 4;
    const int pair = blockIdx.x & 15;
    const half2 z = __float2half2_rn(0.f);

    if (role == 0) {
        // ================= memory-network scan (R10 kC body + publish) =========
        uint4* fS = (uint4*)sm;
        uint4* aS = (uint4*)(sm + 65536);
        uint4* eS = (uint4*)(sm + 98304);
        uint4* adS = (uint4*)(sm + 131072);
        uint4* xh4 = (uint4*)(sm + 163840);
        uint4* fh4 = (uint4*)(sm + 163840 + 1088);
        uint4* yh4 = (uint4*)(sm + 163840 + 1664);
        float* wbuf = (float*)(sm + 163840 + 2240);
        half2* xh2 = (half2*)xh4;
        half2* fh2 = (half2*)fh4;
        half2* yh2 = (half2*)yh4;
        const int o = tid >> 1, p = tid & 1;
        const int b0 = pair * 2;

        for (int i = tid; i < 128 * 128; i += 256) {
            const int jp = i >> 7, oo = i & 127;
            ((half2*)fS)[(((jp >> 2) * 128 + oo) << 2) + (jp & 3)] =
                __floats2half2_rn(fW[oo * 256 + 2 * jp], fW[oo * 256 + 2 * jp + 1]);
        }
        for (int i = tid; i < 64 * 128; i += 256) {
            const int jp = i >> 7, oo = i & 127;
            const int d = (((jp >> 2) * 128 + oo) << 2) + (jp & 3);
            ((half2*)aS)[d] =
                __floats2half2_rn(aW[oo * AWC + NUMC + 2 * jp], aW[oo * AWC + NUMC + 2 * jp + 1]);
            ((half2*)eS)[d] = __floats2half2_rn(eW[oo * 128 + 2 * jp], eW[oo * 128 + 2 * jp + 1]);
            ((half2*)adS)[d] =
                __floats2half2_rn(addW[oo * 128 + 2 * jp], addW[oo * 128 + 2 * jp + 1]);
        }
        if (tid < 24) {
            const int slot = tid / 6, kk = tid % 6;
            wbuf[(slot >> 1) * 112 + (slot & 1) * 56 + 50 + kk] = 0.f;
        }
        const float bfv = fb[o], bav = ab[o], bev = eb[o], badv = addb[o];
        float Mv[56];
#pragma unroll
        for (int m = 0; m < MM; m++) Mv[m] = Mv0[m * DD + o];
#pragma unroll
        for (int m = MM; m < 56; m++) Mv[m] = 0.f;
        __syncthreads();

        const int xbase = p * 132;
        const int fbase = p * 68;
        const int x4 = p * 33, f4 = p * 17;

        for (int t = 0; t < TT; t++) {
            const int idx0 = b0 * TT + t, idx1 = idx0 + TT;
            const int idxp = p ? idx1 : idx0;
            const int par = (t & 1) * 112;
            if (tid < MM) wbuf[par + tid] = g_w[idx0 * MM + tid];
            else if (tid >= 128 && tid < 128 + MM)
                wbuf[par + 56 + tid - 128] = g_w[idx1 * MM + tid - 128];
            {
                const float kv = g_k[idxp * DD + o];
                const float kn = __shfl_xor_sync(0xffffffffu, kv, 2);
                if (!(tid & 2)) xh2[xbase + 64 + (o >> 1)] = __floats2half2_rn(kv, kn);
            }
            const float yqv = g_yq[idxp * DD + o];
            __syncthreads();  // B1

            const float4* w4 = (const float4*)&wbuf[par + p * 56];
            float r0 = 0.f, r1 = 0.f, r2 = 0.f, r3 = 0.f;
#pragma unroll
            for (int c = 0; c < 14; c++) {
                const float4 wv = w4[c];
                r0 = fmaf(wv.x, Mv[4 * c], r0);
                r1 = fmaf(wv.y, Mv[4 * c + 1], r1);
                r2 = fmaf(wv.z, Mv[4 * c + 2], r2);
                r3 = fmaf(wv.w, Mv[4 * c + 3], r3);
            }
            {
                const float rv = (r0 + r1) + (r2 + r3);
                const float rn = __shfl_xor_sync(0xffffffffu, rv, 2);
                if (!(tid & 2)) xh2[xbase + (o >> 1)] = __floats2half2_rn(rv, rn);
            }
            __syncthreads();  // B2

            half2 F[8] = {z, z, z, z, z, z, z, z};
#pragma unroll
            for (int j = 0; j < 32; j++) {
                const uint4 wv = fS[j * 128 + o];
                const uint4 xv = xh4[x4 + j];
                const int q4 = (j & 1) << 2;
                F[q4 + 0] = __hfma2(as_h2(wv.x), as_h2(xv.x), F[q4 + 0]);
                F[q4 + 1] = __hfma2(as_h2(wv.y), as_h2(xv.y), F[q4 + 1]);
                F[q4 + 2] = __hfma2(as_h2(wv.z), as_h2(xv.z), F[q4 + 2]);
                F[q4 + 3] = __hfma2(as_h2(wv.w), as_h2(xv.w), F[q4 + 3]);
            }
            float sf = bfv;
#pragma unroll
            for (int qq = 0; qq < 8; qq++) sf += h2sumf(F[qq]);
            const float fv = ftanh(sf);
            g_f[idxp * DD + o] = fv;
            {
                const float fn = __shfl_xor_sync(0xffffffffu, fv, 2);
                if (!(tid & 2)) fh2[fbase + (o >> 1)] = __floats2half2_rn(fv, fn);
            }
            __syncthreads();  // B3 — g_f complete for step t
            if (tid == 0) {
                __threadfence();
                *((volatile int*)&g_prog[pair]) = t + 1;
            }

            half2 Y[4] = {z, z, z, z};
#pragma unroll
            for (int j = 0; j < 16; j++) {
                const uint4 wv = aS[j * 128 + o];
                const uint4 xv = fh4[f4 + j];
                Y[0] = __hfma2(as_h2(wv.x), as_h2(xv.x), Y[0]);
                Y[1] = __hfma2(as_h2(wv.y), as_h2(xv.y), Y[1]);
                Y[2] = __hfma2(as_h2(wv.z), as_h2(xv.z), Y[2]);
                Y[3] = __hfma2(as_h2(wv.w), as_h2(xv.w), Y[3]);
            }
            float yv = bav + yqv;
#pragma unroll
            for (int qq = 0; qq < 4; qq++) yv += h2sumf(Y[qq]);
            {
                const float yn = __shfl_xor_sync(0xffffffffu, yv, 2);
                if (!(tid & 2)) yh2[fbase + (o >> 1)] = __floats2half2_rn(yv, yn);
            }
            __syncthreads();  // B4

            half2 E[4] = {z, z, z, z}, Dg[4] = {z, z, z, z};
#pragma unroll
            for (int j = 0; j < 16; j++) {
                const uint4 we = eS[j * 128 + o];
                const uint4 wa = adS[j * 128 + o];
                const uint4 xv = yh4[f4 + j];
                E[0] = __hfma2(as_h2(we.x), as_h2(xv.x), E[0]);
                E[1] = __hfma2(as_h2(we.y), as_h2(xv.y), E[1]);
                E[2] = __hfma2(as_h2(we.z), as_h2(xv.z), E[2]);
                E[3] = __hfma2(as_h2(we.w), as_h2(xv.w), E[3]);
                Dg[0] = __hfma2(as_h2(wa.x), as_h2(xv.x), Dg[0]);
                Dg[1] = __hfma2(as_h2(wa.y), as_h2(xv.y), Dg[1]);
                Dg[2] = __hfma2(as_h2(wa.z), as_h2(xv.z), Dg[2]);
                Dg[3] = __hfma2(as_h2(wa.w), as_h2(xv.w), Dg[3]);
            }
            float se = bev, sd = badv;
#pragma unroll
            for (int qq = 0; qq < 4; qq++) {
                se += h2sumf(E[qq]);
                sd += h2sumf(Dg[qq]);
            }
            const float ev = sigf(se), av = ftanh(sd);
#pragma unroll
            for (int c = 0; c < 14; c++) {
                const float4 wv = w4[c];
                Mv[4 * c] = fmaf(wv.x, fmaf(-ev, Mv[4 * c], av), Mv[4 * c]);
                Mv[4 * c + 1] = fmaf(wv.y, fmaf(-ev, Mv[4 * c + 1], av), Mv[4 * c + 1]);
                Mv[4 * c + 2] = fmaf(wv.z, fmaf(-ev, Mv[4 * c + 2], av), Mv[4 * c + 2]);
                Mv[4 * c + 3] = fmaf(wv.w, fmaf(-ev, Mv[4 * c + 3], av), Mv[4 * c + 3]);
            }
        }
    } else if (role == 1) {
        // ================= gi worker: gi = f @ Wih.T + (bih+bhh) ===============
        uint4* wS = (uint4*)sm;                      // [16][512] = 128KB
        uint4* fh4 = (uint4*)(sm + 131072);          // [34]: b0@0, b1@17
        float* bias = (float*)(sm + 131072 + 544);   // [512]
        half2* fh2 = (half2*)fh4;
        const int b0 = pair * 2;

        for (int i = tid; i < 64 * G4; i += 256) {
            const int jp = i >> 9, g = i & 511;
            ((half2*)wS)[(((jp >> 2) * G4 + g) << 2) + (jp & 3)] =
                __floats2half2_rn(Wih[g * DD + 2 * jp], Wih[g * DD + 2 * jp + 1]);
        }
        for (int g = tid; g < G4; g += 256) bias[g] = bih[g] + bhh[g];
        __syncthreads();

        const int g0 = tid, g1 = tid + 256;
        const float bs0 = bias[g0], bs1 = bias[g1];
        for (int t = 0; t < TT; t++) {
            wait_ge(&g_prog[pair], t + 1);
            const int idx0 = b0 * TT + t, idx1 = idx0 + TT;
            {
                const int bb = tid >> 7, d = tid & 127;
                const float fv = g_f[(size_t)(bb ? idx1 : idx0) * DD + d];
                const float fn = __shfl_xor_sync(0xffffffffu, fv, 1);
                if (!(d & 1)) fh2[bb * 68 + (d >> 1)] = __floats2half2_rn(fv, fn);
            }
            __syncthreads();  // staging done

            half2 a00[2] = {z, z}, a01[2] = {z, z}, a10[2] = {z, z}, a11[2] = {z, z};
#pragma unroll
            for (int j = 0; j < 16; j++) {
                const uint4 x0 = fh4[j];
                const uint4 x1 = fh4[17 + j];
                const uint4 w0 = wS[j * G4 + g0];
                const uint4 w1 = wS[j * G4 + g1];
                const int q = j & 1;
                a00[q] = __hfma2(as_h2(w0.x), as_h2(x0.x), a00[q]);
                a00[q] = __hfma2(as_h2(w0.y), as_h2(x0.y), a00[q]);
                a00[q] = __hfma2(as_h2(w0.z), as_h2(x0.z), a00[q]);
                a00[q] = __hfma2(as_h2(w0.w), as_h2(x0.w), a00[q]);
                a01[q] = __hfma2(as_h2(w0.x), as_h2(x1.x), a01[q]);
                a01[q] = __hfma2(as_h2(w0.y), as_h2(x1.y), a01[q]);
                a01[q] = __hfma2(as_h2(w0.z), as_h2(x1.z), a01[q]);
                a01[q] = __hfma2(as_h2(w0.w), as_h2(x1.w), a01[q]);
                a10[q] = __hfma2(as_h2(w1.x), as_h2(x0.x), a10[q]);
                a10[q] = __hfma2(as_h2(w1.y), as_h2(x0.y), a10[q]);
                a10[q] = __hfma2(as_h2(w1.z), as_h2(x0.z), a10[q]);
                a10[q] = __hfma2(as_h2(w1.w), as_h2(x0.w), a10[q]);
                a11[q] = __hfma2(as_h2(w1.x), as_h2(x1.x), a11[q]);
                a11[q] = __hfma2(as_h2(w1.y), as_h2(x1.y), a11[q]);
                a11[q] = __hfma2(as_h2(w1.z), as_h2(x1.z), a11[q]);
                a11[q] = __hfma2(as_h2(w1.w), as_h2(x1.w), a11[q]);
            }
            g_gi[(size_t)idx0 * G4 + g0] = bs0 + h2sumf(a00[0]) + h2sumf(a00[1]);
            g_gi[(size_t)idx1 * G4 + g0] = bs0 + h2sumf(a01[0]) + h2sumf(a01[1]);
            g_gi[(size_t)idx0 * G4 + g1] = bs1 + h2sumf(a10[0]) + h2sumf(a10[1]);
            g_gi[(size_t)idx1 * G4 + g1] = bs1 + h2sumf(a11[0]) + h2sumf(a11[1]);
            __syncthreads();  // all gi STGs issued + fh4 reads done
            if (tid == 0) {
                __threadfence();
                *((volatile int*)&g_prog[NPAIR + pair]) = t + 1;
            }
        }
    } else {
        // ================= LSTM scan (R10 kE body + poll) ======================
        uint4* wS = (uint4*)sm;                   // [16][512]
        uint4* hh4 = (uint4*)(sm + 131072);       // [33]
        half2* hh2 = (half2*)hh4;
        const int d = tid >> 1, p = tid & 1;
        const int b0 = pair * 2;

        for (int i = tid; i < 64 * G4; i += 256) {
            const int jp = i >> 9, g = i & 511;
            ((half2*)wS)[(((jp >> 2) * G4 + g) << 2) + (jp & 3)] =
                __floats2half2_rn(Whh[g * DD + 2 * jp], Whh[g * DD + 2 * jp + 1]);
        }
        float h = 0.f, c = 0.f;
        __syncthreads();

        const int hbase = p * 68;
        const int h4 = p * 17;
        const int bB = b0 + p;

        for (int t = 0; t < TT; t++) {
            const int idxp = bB * TT + t;
            float cin;
            {
                float hv;
                if (g_match[idxp]) {
                    const int pv = g_prev[idxp];
                    hv = g_H[(size_t)(bB * TT + pv) * DD + d];
                    cin = g_C[(size_t)(bB * TT + pv) * DD + d];
                } else {
                    hv = h; cin = c;
                }
                const float hn = __shfl_xor_sync(0xffffffffu, hv, 2);
                if (!(tid & 2)) hh2[hbase + (d >> 1)] = __floats2half2_rn(hv, hn);
            }
            wait_ge(&g_prog[NPAIR + pair], t + 1);
            float gI = g_gi[(size_t)idxp * G4 + d];
            float gF = g_gi[(size_t)idxp * G4 + 128 + d];
            float gG = g_gi[(size_t)idxp * G4 + 256 + d];
            float gO = g_gi[(size_t)idxp * G4 + 384 + d];
            __syncthreads();  // A

            half2 ai[2] = {z, z}, af[2] = {z, z}, ag[2] = {z, z}, ao[2] = {z, z};
#pragma unroll
            for (int j = 0; j < 16; j++) {
                const uint4 xv = hh4[h4 + j];
                const uint4 wi = wS[j * G4 + d];
                const uint4 wf = wS[j * G4 + 128 + d];
                const uint4 wg = wS[j * G4 + 256 + d];
                const uint4 wo = wS[j * G4 + 384 + d];
                const int q = j & 1;
                ai[q] = __hfma2(as_h2(wi.x), as_h2(xv.x), ai[q]);
                ai[q] = __hfma2(as_h2(wi.y), as_h2(xv.y), ai[q]);
                ai[q] = __hfma2(as_h2(wi.z), as_h2(xv.z), ai[q]);
                ai[q] = __hfma2(as_h2(wi.w), as_h2(xv.w), ai[q]);
                af[q] = __hfma2(as_h2(wf.x), as_h2(xv.x), af[q]);
                af[q] = __hfma2(as_h2(wf.y), as_h2(xv.y), af[q]);
                af[q] = __hfma2(as_h2(wf.z), as_h2(xv.z), af[q]);
                af[q] = __hfma2(as_h2(wf.w), as_h2(xv.w), af[q]);
                ag[q] = __hfma2(as_h2(wg.x), as_h2(xv.x), ag[q]);
                ag[q] = __hfma2(as_h2(wg.y), as_h2(xv.y), ag[q]);
                ag[q] = __hfma2(as_h2(wg.z), as_h2(xv.z), ag[q]);
                ag[q] = __hfma2(as_h2(wg.w), as_h2(xv.w), ag[q]);
                ao[q] = __hfma2(as_h2(wo.x), as_h2(xv.x), ao[q]);
                ao[q] = __hfma2(as_h2(wo.y), as_h2(xv.y), ao[q]);
                ao[q] = __hfma2(as_h2(wo.z), as_h2(xv.z), ao[q]);
                ao[q] = __hfma2(as_h2(wo.w), as_h2(xv.w), ao[q]);
            }
            gI += h2sumf(ai[0]) + h2sumf(ai[1]);
            gF += h2sumf(af[0]) + h2sumf(af[1]);
            gG += h2sumf(ag[0]) + h2sumf(ag[1]);
            gO += h2sumf(ao[0]) + h2sumf(ao[1]);
            c = sigf(gF) * cin + sigf(gI) * ftanh(gG);
            h = sigf(gO) * ftanh(c);
            g_H[(size_t)idxp * DD + d] = h;
            g_C[(size_t)idxp * DD + d] = c;
            __syncthreads();  // B
        }
    }
}

// ---------------- Kernel F: out = sigmoid(H . pW + pb) -------------------------
__global__ __launch_bounds__(256) void kF(const float* __restrict__ pW,
                                          const float* __restrict__ pb,
                                          float* __restrict__ out) {
    const int gw = blockIdx.x * 8 + (threadIdx.x >> 5);
    const int lane = threadIdx.x & 31;
    const float4 hv = ((const float4*)(g_H + (size_t)gw * DD))[lane];
    const float4 pv = ((const float4*)pW)[lane];
    float v = hv.x * pv.x + hv.y * pv.y + hv.z * pv.z + hv.w * pv.w;
    v = warp_sum(v);
    if (lane == 0) out[gw] = sigf(v + pb[0]);
}

// ---------------- launch ----------------
extern "C" void kernel_launch(void* const* d_in, const int* in_sizes, int n_in,
                              void* d_out, int out_size) {
    const int* q = (const int*)d_in[0];
    const int* r = (const int*)d_in[1];
    const float* k_emb = (const float*)d_in[2];
    const float* Mk = (const float*)d_in[3];
    const float* Mv0 = (const float*)d_in[4];
    const float* fW = (const float*)d_in[5];
    const float* fb = (const float*)d_in[6];
    const float* aW = (const float*)d_in[7];
    const float* ab = (const float*)d_in[8];
    const float* eW = (const float*)d_in[9];
    const float* eb = (const float*)d_in[10];
    const float* addW = (const float*)d_in[11];
    const float* addb = (const float*)d_in[12];
    const float* Wih = (const float*)d_in[13];
    const float* Whh = (const float*)d_in[14];
    const float* bih = (const float*)d_in[15];
    const float* bhh = (const float*)d_in[16];
    const float* pW = (const float*)d_in[17];
    const float* pb = (const float*)d_in[18];
    float* out = (float*)d_out;

    cudaFuncSetAttribute(kScan, cudaFuncAttributeMaxDynamicSharedMemorySize, SC_SMEM);

    kA<<<256, 256>>>(q, r, k_emb, Mk, aW);
    kB<<<RR / 8, 256>>>();
    kScan<<<3 * NPAIR, 256, SC_SMEM>>>(fW, fb, aW, ab, eW, eb, addW, addb, Mv0,
                                       Wih, bih, bhh, Whh);
    kF<<<RR / 8, 256>>>(pW, pb, out);
}

// round 14
// speedup vs baseline: 2.4481x; 1.0229x over previous
#include <cuda_runtime.h>
#include <cuda_fp16.h>

#define BSZ 32
#define TT 512
#define DD 128
#define MM 50
#define NUMC 4096
#define AWC (NUMC + DD)
#define G4 512
#define RR (BSZ * TT)
#define NPAIR 16
#define FLAGSTRIDE 32

// ---------------- scratch (static device arrays; no allocation) ----------------
__device__ float g_k[RR * DD];
__device__ float g_yq[RR * DD];
__device__ float g_w[RR * MM];
__device__ unsigned long long g_pack[RR * 2];
__device__ int g_prev[RR];
__device__ int g_match[RR];
__device__ float g_f[RR * DD];
__device__ float g_gi[RR * G4];
__device__ float g_H[RR * DD];
__device__ float g_C[RR * DD];
__device__ int g_prog[2 * NPAIR * FLAGSTRIDE];  // each flag on its own 128B line

__device__ __forceinline__ float warp_sum(float v) {
#pragma unroll
    for (int o = 16; o; o >>= 1) v += __shfl_xor_sync(0xffffffffu, v, o);
    return v;
}
__device__ __forceinline__ half2 as_h2(unsigned u) { return *reinterpret_cast<half2*>(&u); }
__device__ __forceinline__ float sigf(float x) { return 1.f / (1.f + __expf(-x)); }
__device__ __forceinline__ float h2sumf(half2 v) {
    const float2 e = __half22float2(v);
    return e.x + e.y;
}
__device__ __forceinline__ float ftanh(float x) {
    float y;
    asm("tanh.approx.f32 %0, %1;" : "=f"(y) : "f"(x));
    return y;
}
// publish: call AFTER __syncthreads() that closes the data writes; tid0 only.
__device__ __forceinline__ void publish(int* flag, int v) {
    asm volatile("fence.release.gpu;" ::: "memory");
    asm volatile("st.relaxed.gpu.global.s32 [%0], %1;" :: "l"(flag), "r"(v) : "memory");
}
// consume: spin until *flag >= v, then acquire-fence.
__device__ __forceinline__ void wait_ge(const int* flag, int v) {
    int x, spins = 0;
    while (true) {
        asm volatile("ld.relaxed.gpu.global.s32 %0, [%1];" : "=r"(x) : "l"(flag) : "memory");
        if (x >= v) break;
        if (++spins > 64) __nanosleep(20);
    }
    asm volatile("fence.acquire.gpu;" ::: "memory");
}

// ---------------- Kernel A: gather + logits + softmax + pack + flag-zero -------
__global__ __launch_bounds__(256) void kA(const int* __restrict__ q,
                                          const int* __restrict__ r,
                                          const float* __restrict__ k_emb,
                                          const float* __restrict__ Mk,
                                          const float* __restrict__ aW) {
    __shared__ float sMk[MM * DD];
    __shared__ float sk[DD];
    __shared__ float slog[MM];
    const int tid = threadIdx.x;
    if (blockIdx.x == 0 && tid < 2 * NPAIR) g_prog[tid * FLAGSTRIDE] = 0;
    for (int i = tid; i < MM * DD; i += 256) sMk[i] = Mk[i];
    const int base = blockIdx.x * 64;
    const int warp = tid >> 5, lane = tid & 31;

    for (int p = 0; p < 64; p++) {
        const int idx = base + p;
        __syncthreads();
        if (tid < DD) {
            const int qv = q[idx];
            const float kv = k_emb[qv * DD + tid];
            sk[tid] = kv;
            g_k[idx * DD + tid] = kv;
            g_yq[idx * DD + tid] = aW[tid * AWC + qv] * (float)r[idx];
        }
        __syncthreads();
        for (int m = warp; m < MM; m += 8) {
            float s = 0.f;
#pragma unroll
            for (int c = 0; c < 4; c++) s = fmaf(sk[c * 32 + lane], sMk[m * DD + c * 32 + lane], s);
            s = warp_sum(s);
            if (lane == 0) slog[m] = s;
        }
        __syncthreads();
        if (warp == 0) {
            float l0 = (lane < MM) ? slog[lane] : -1e30f;
            float l1 = (lane + 32 < MM) ? slog[lane + 32] : -1e30f;
            float mx = fmaxf(l0, l1);
#pragma unroll
            for (int o = 16; o; o >>= 1) mx = fmaxf(mx, __shfl_xor_sync(0xffffffffu, mx, o));
            float e0 = (lane < MM) ? expf(l0 - mx) : 0.f;
            float e1 = (lane + 32 < MM) ? expf(l1 - mx) : 0.f;
            float ssum = warp_sum(e0 + e1);
            float w0 = e0 / ssum, w1 = e1 / ssum;
            if (lane < MM) g_w[idx * MM + lane] = w0;
            if (lane + 32 < MM) g_w[idx * MM + lane + 32] = w1;
            const float ta = 0.075f;
            const float dba = (float)(0.088 - 0.075);
            const float dcb = (float)(1.0 - 0.088);
            float tw0 = fmaxf(fminf((w0 - ta) / dba, (1.0f - w0) / dcb), 0.f);
            float tw1 = fmaxf(fminf((w1 - ta) / dba, (1.0f - w1) / dcb), 0.f);
            int c0 = (lane < MM) ? (tw0 >= 0.6f ? 2 : (tw0 >= 0.1f ? 1 : 0)) : 0;
            int c1 = (lane + 32 < MM) ? (tw1 >= 0.6f ? 2 : (tw1 >= 0.1f ? 1 : 0)) : 0;
            unsigned b00 = __ballot_sync(0xffffffffu, c0 & 1);
            unsigned b01 = __ballot_sync(0xffffffffu, c0 >> 1);
            unsigned b10 = __ballot_sync(0xffffffffu, c1 & 1);
            unsigned b11 = __ballot_sync(0xffffffffu, c1 >> 1);
            if (lane == 0) {
                g_pack[idx * 2 + 0] = (unsigned long long)b00 | ((unsigned long long)b01 << 32);
                g_pack[idx * 2 + 1] = (unsigned long long)b10 | ((unsigned long long)b11 << 32);
            }
        }
    }
}

// ---------------- Kernel B: matched/prev via warp ballot backward scan ---------
__global__ __launch_bounds__(256) void kB() {
    const int gw = blockIdx.x * 8 + (threadIdx.x >> 5);
    const int lane = threadIdx.x & 31;
    const int b = gw / TT, i = gw % TT;
    const unsigned long long m0 = g_pack[gw * 2], m1 = g_pack[gw * 2 + 1];
    const unsigned long long* rp = &g_pack[(size_t)b * TT * 2];
    int prev = 0, matched = 0;
    for (int base = i - 1; base >= 0; base -= 32) {
        const int j = base - lane;
        const bool eq = (j >= 0) && (rp[j * 2] == m0) && (rp[j * 2 + 1] == m1);
        const unsigned msk = __ballot_sync(0xffffffffu, eq);
        if (msk) { matched = 1; prev = base - (__ffs(msk) - 1); break; }
    }
    if (lane == 0) { g_prev[gw] = prev; g_match[gw] = matched; }
}

// ---------------- kScan: persistent pipelined mega-kernel ----------------------
// 48 blocks x 256 threads. role = blockIdx.x>>4: 0=memnet(kC), 1=gi worker, 2=lstm(kE)
#define SC_SMEM (163840 + 2240 + 896)
__global__ __launch_bounds__(256) void kScan(const float* __restrict__ fW,
                                             const float* __restrict__ fb,
                                             const float* __restrict__ aW,
                                             const float* __restrict__ ab,
                                             const float* __restrict__ eW,
                                             const float* __restrict__ eb,
                                             const float* __restrict__ addW,
                                             const float* __restrict__ addb,
                                             const float* __restrict__ Mv0,
                                             const float* __restrict__ Wih,
                                             const float* __restrict__ bih,
                                             const float* __restrict__ bhh,
                                             const float* __restrict__ Whh) {
    extern __shared__ char sm[];
    const int tid = threadIdx.x;
    const int role = blockIdx.x >> 4;
    const int pair = blockIdx.x & 15;
    const half2 z = __float2half2_rn(0.f);

    if (role == 0) {
        // ================= memory-network scan (R10 kC body + publish) =========
        uint4* fS = (uint4*)sm;
        uint4* aS = (uint4*)(sm + 65536);
        uint4* eS = (uint4*)(sm + 98304);
        uint4* adS = (uint4*)(sm + 131072);
        uint4* xh4 = (uint4*)(sm + 163840);
        uint4* fh4 = (uint4*)(sm + 163840 + 1088);
        uint4* yh4 = (uint4*)(sm + 163840 + 1664);
        float* wbuf = (float*)(sm + 163840 + 2240);
        half2* xh2 = (half2*)xh4;
        half2* fh2 = (half2*)fh4;
        half2* yh2 = (half2*)yh4;
        const int o = tid >> 1, p = tid & 1;
        const int b0 = pair * 2;

        for (int i = tid; i < 128 * 128; i += 256) {
            const int jp = i >> 7, oo = i & 127;
            ((half2*)fS)[(((jp >> 2) * 128 + oo) << 2) + (jp & 3)] =
                __floats2half2_rn(fW[oo * 256 + 2 * jp], fW[oo * 256 + 2 * jp + 1]);
        }
        for (int i = tid; i < 64 * 128; i += 256) {
            const int jp = i >> 7, oo = i & 127;
            const int d = (((jp >> 2) * 128 + oo) << 2) + (jp & 3);
            ((half2*)aS)[d] =
                __floats2half2_rn(aW[oo * AWC + NUMC + 2 * jp], aW[oo * AWC + NUMC + 2 * jp + 1]);
            ((half2*)eS)[d] = __floats2half2_rn(eW[oo * 128 + 2 * jp], eW[oo * 128 + 2 * jp + 1]);
            ((half2*)adS)[d] =
                __floats2half2_rn(addW[oo * 128 + 2 * jp], addW[oo * 128 + 2 * jp + 1]);
        }
        if (tid < 24) {
            const int slot = tid / 6, kk = tid % 6;
            wbuf[(slot >> 1) * 112 + (slot & 1) * 56 + 50 + kk] = 0.f;
        }
        const float bfv = fb[o], bav = ab[o], bev = eb[o], badv = addb[o];
        float Mv[56];
#pragma unroll
        for (int m = 0; m < MM; m++) Mv[m] = Mv0[m * DD + o];
#pragma unroll
        for (int m = MM; m < 56; m++) Mv[m] = 0.f;
        __syncthreads();

        const int xbase = p * 132;
        const int fbase = p * 68;
        const int x4 = p * 33, f4 = p * 17;

        for (int t = 0; t < TT; t++) {
            const int idx0 = b0 * TT + t, idx1 = idx0 + TT;
            const int idxp = p ? idx1 : idx0;
            const int par = (t & 1) * 112;
            if (tid < MM) wbuf[par + tid] = g_w[idx0 * MM + tid];
            else if (tid >= 128 && tid < 128 + MM)
                wbuf[par + 56 + tid - 128] = g_w[idx1 * MM + tid - 128];
            {
                const float kv = g_k[idxp * DD + o];
                const float kn = __shfl_xor_sync(0xffffffffu, kv, 2);
                if (!(tid & 2)) xh2[xbase + 64 + (o >> 1)] = __floats2half2_rn(kv, kn);
            }
            const float yqv = g_yq[idxp * DD + o];
            __syncthreads();  // B1

            const float4* w4 = (const float4*)&wbuf[par + p * 56];
            float r0 = 0.f, r1 = 0.f, r2 = 0.f, r3 = 0.f;
#pragma unroll
            for (int c = 0; c < 14; c++) {
                const float4 wv = w4[c];
                r0 = fmaf(wv.x, Mv[4 * c], r0);
                r1 = fmaf(wv.y, Mv[4 * c + 1], r1);
                r2 = fmaf(wv.z, Mv[4 * c + 2], r2);
                r3 = fmaf(wv.w, Mv[4 * c + 3], r3);
            }
            {
                const float rv = (r0 + r1) + (r2 + r3);
                const float rn = __shfl_xor_sync(0xffffffffu, rv, 2);
                if (!(tid & 2)) xh2[xbase + (o >> 1)] = __floats2half2_rn(rv, rn);
            }
            __syncthreads();  // B2

            half2 F[8] = {z, z, z, z, z, z, z, z};
#pragma unroll
            for (int j = 0; j < 32; j++) {
                const uint4 wv = fS[j * 128 + o];
                const uint4 xv = xh4[x4 + j];
                const int q4 = (j & 1) << 2;
                F[q4 + 0] = __hfma2(as_h2(wv.x), as_h2(xv.x), F[q4 + 0]);
                F[q4 + 1] = __hfma2(as_h2(wv.y), as_h2(xv.y), F[q4 + 1]);
                F[q4 + 2] = __hfma2(as_h2(wv.z), as_h2(xv.z), F[q4 + 2]);
                F[q4 + 3] = __hfma2(as_h2(wv.w), as_h2(xv.w), F[q4 + 3]);
            }
            float sf = bfv;
#pragma unroll
            for (int qq = 0; qq < 8; qq++) sf += h2sumf(F[qq]);
            const float fv = ftanh(sf);
            g_f[idxp * DD + o] = fv;
            {
                const float fn = __shfl_xor_sync(0xffffffffu, fv, 2);
                if (!(tid & 2)) fh2[fbase + (o >> 1)] = __floats2half2_rn(fv, fn);
            }
            __syncthreads();  // B3 — g_f complete for step t
            if (tid == 0) publish(&g_prog[pair * FLAGSTRIDE], t + 1);

            half2 Y[4] = {z, z, z, z};
#pragma unroll
            for (int j = 0; j < 16; j++) {
                const uint4 wv = aS[j * 128 + o];
                const uint4 xv = fh4[f4 + j];
                Y[0] = __hfma2(as_h2(wv.x), as_h2(xv.x), Y[0]);
                Y[1] = __hfma2(as_h2(wv.y), as_h2(xv.y), Y[1]);
                Y[2] = __hfma2(as_h2(wv.z), as_h2(xv.z), Y[2]);
                Y[3] = __hfma2(as_h2(wv.w), as_h2(xv.w), Y[3]);
            }
            float yv = bav + yqv;
#pragma unroll
            for (int qq = 0; qq < 4; qq++) yv += h2sumf(Y[qq]);
            {
                const float yn = __shfl_xor_sync(0xffffffffu, yv, 2);
                if (!(tid & 2)) yh2[fbase + (o >> 1)] = __floats2half2_rn(yv, yn);
            }
            __syncthreads();  // B4

            half2 E[4] = {z, z, z, z}, Dg[4] = {z, z, z, z};
#pragma unroll
            for (int j = 0; j < 16; j++) {
                const uint4 we = eS[j * 128 + o];
                const uint4 wa = adS[j * 128 + o];
                const uint4 xv = yh4[f4 + j];
                E[0] = __hfma2(as_h2(we.x), as_h2(xv.x), E[0]);
                E[1] = __hfma2(as_h2(we.y), as_h2(xv.y), E[1]);
                E[2] = __hfma2(as_h2(we.z), as_h2(xv.z), E[2]);
                E[3] = __hfma2(as_h2(we.w), as_h2(xv.w), E[3]);
                Dg[0] = __hfma2(as_h2(wa.x), as_h2(xv.x), Dg[0]);
                Dg[1] = __hfma2(as_h2(wa.y), as_h2(xv.y), Dg[1]);
                Dg[2] = __hfma2(as_h2(wa.z), as_h2(xv.z), Dg[2]);
                Dg[3] = __hfma2(as_h2(wa.w), as_h2(xv.w), Dg[3]);
            }
            float se = bev, sd = badv;
#pragma unroll
            for (int qq = 0; qq < 4; qq++) {
                se += h2sumf(E[qq]);
                sd += h2sumf(Dg[qq]);
            }
            const float ev = sigf(se), av = ftanh(sd);
#pragma unroll
            for (int c = 0; c < 14; c++) {
                const float4 wv = w4[c];
                Mv[4 * c] = fmaf(wv.x, fmaf(-ev, Mv[4 * c], av), Mv[4 * c]);
                Mv[4 * c + 1] = fmaf(wv.y, fmaf(-ev, Mv[4 * c + 1], av), Mv[4 * c + 1]);
                Mv[4 * c + 2] = fmaf(wv.z, fmaf(-ev, Mv[4 * c + 2], av), Mv[4 * c + 2]);
                Mv[4 * c + 3] = fmaf(wv.w, fmaf(-ev, Mv[4 * c + 3], av), Mv[4 * c + 3]);
            }
        }
    } else if (role == 1) {
        // ================= gi worker: gi = f @ Wih.T + (bih+bhh) ===============
        uint4* wS = (uint4*)sm;                      // [16][512] = 128KB
        uint4* fh4 = (uint4*)(sm + 131072);          // [34]: b0@0, b1@17
        float* bias = (float*)(sm + 131072 + 544);   // [512]
        half2* fh2 = (half2*)fh4;
        const int b0 = pair * 2;

        for (int i = tid; i < 64 * G4; i += 256) {
            const int jp = i >> 9, g = i & 511;
            ((half2*)wS)[(((jp >> 2) * G4 + g) << 2) + (jp & 3)] =
                __floats2half2_rn(Wih[g * DD + 2 * jp], Wih[g * DD + 2 * jp + 1]);
        }
        for (int g = tid; g < G4; g += 256) bias[g] = bih[g] + bhh[g];
        __syncthreads();

        const int g0 = tid, g1 = tid + 256;
        const float bs0 = bias[g0], bs1 = bias[g1];
        for (int t = 0; t < TT; t++) {
            if (tid == 0) wait_ge(&g_prog[pair * FLAGSTRIDE], t + 1);
            __syncthreads();
            const int idx0 = b0 * TT + t, idx1 = idx0 + TT;
            {
                const int bb = tid >> 7, d = tid & 127;
                const float fv = g_f[(size_t)(bb ? idx1 : idx0) * DD + d];
                const float fn = __shfl_xor_sync(0xffffffffu, fv, 1);
                if (!(d & 1)) fh2[bb * 68 + (d >> 1)] = __floats2half2_rn(fv, fn);
            }
            __syncthreads();  // staging done

            half2 a00[2] = {z, z}, a01[2] = {z, z}, a10[2] = {z, z}, a11[2] = {z, z};
#pragma unroll
            for (int j = 0; j < 16; j++) {
                const uint4 x0 = fh4[j];
                const uint4 x1 = fh4[17 + j];
                const uint4 w0 = wS[j * G4 + g0];
                const uint4 w1 = wS[j * G4 + g1];
                const int q = j & 1;
                a00[q] = __hfma2(as_h2(w0.x), as_h2(x0.x), a00[q]);
                a00[q] = __hfma2(as_h2(w0.y), as_h2(x0.y), a00[q]);
                a00[q] = __hfma2(as_h2(w0.z), as_h2(x0.z), a00[q]);
                a00[q] = __hfma2(as_h2(w0.w), as_h2(x0.w), a00[q]);
                a01[q] = __hfma2(as_h2(w0.x), as_h2(x1.x), a01[q]);
                a01[q] = __hfma2(as_h2(w0.y), as_h2(x1.y), a01[q]);
                a01[q] = __hfma2(as_h2(w0.z), as_h2(x1.z), a01[q]);
                a01[q] = __hfma2(as_h2(w0.w), as_h2(x1.w), a01[q]);
                a10[q] = __hfma2(as_h2(w1.x), as_h2(x0.x), a10[q]);
                a10[q] = __hfma2(as_h2(w1.y), as_h2(x0.y), a10[q]);
                a10[q] = __hfma2(as_h2(w1.z), as_h2(x0.z), a10[q]);
                a10[q] = __hfma2(as_h2(w1.w), as_h2(x0.w), a10[q]);
                a11[q] = __hfma2(as_h2(w1.x), as_h2(x1.x), a11[q]);
                a11[q] = __hfma2(as_h2(w1.y), as_h2(x1.y), a11[q]);
                a11[q] = __hfma2(as_h2(w1.z), as_h2(x1.z), a11[q]);
                a11[q] = __hfma2(as_h2(w1.w), as_h2(x1.w), a11[q]);
            }
            g_gi[(size_t)idx0 * G4 + g0] = bs0 + h2sumf(a00[0]) + h2sumf(a00[1]);
            g_gi[(size_t)idx1 * G4 + g0] = bs0 + h2sumf(a01[0]) + h2sumf(a01[1]);
            g_gi[(size_t)idx0 * G4 + g1] = bs1 + h2sumf(a10[0]) + h2sumf(a10[1]);
            g_gi[(size_t)idx1 * G4 + g1] = bs1 + h2sumf(a11[0]) + h2sumf(a11[1]);
            __syncthreads();  // all gi STGs issued + fh4 reads done
            if (tid == 0) publish(&g_prog[(NPAIR + pair) * FLAGSTRIDE], t + 1);
        }
    } else {
        // ================= LSTM scan (R10 kE body + poll) ======================
        uint4* wS = (uint4*)sm;                   // [16][512]
        uint4* hh4 = (uint4*)(sm + 131072);       // [33]
        half2* hh2 = (half2*)hh4;
        const int d = tid >> 1, p = tid & 1;
        const int b0 = pair * 2;

        for (int i = tid; i < 64 * G4; i += 256) {
            const int jp = i >> 9, g = i & 511;
            ((half2*)wS)[(((jp >> 2) * G4 + g) << 2) + (jp & 3)] =
                __floats2half2_rn(Whh[g * DD + 2 * jp], Whh[g * DD + 2 * jp + 1]);
        }
        float h = 0.f, c = 0.f;
        __syncthreads();

        const int hbase = p * 68;
        const int h4 = p * 17;
        const int bB = b0 + p;

        for (int t = 0; t < TT; t++) {
            const int idxp = bB * TT + t;
            float cin;
            {
                float hv;
                if (g_match[idxp]) {
                    const int pv = g_prev[idxp];
                    hv = g_H[(size_t)(bB * TT + pv) * DD + d];
                    cin = g_C[(size_t)(bB * TT + pv) * DD + d];
                } else {
                    hv = h; cin = c;
                }
                const float hn = __shfl_xor_sync(0xffffffffu, hv, 2);
                if (!(tid & 2)) hh2[hbase + (d >> 1)] = __floats2half2_rn(hv, hn);
            }
            wait_ge(&g_prog[(NPAIR + pair) * FLAGSTRIDE], t + 1);
            float gI = g_gi[(size_t)idxp * G4 + d];
            float gF = g_gi[(size_t)idxp * G4 + 128 + d];
            float gG = g_gi[(size_t)idxp * G4 + 256 + d];
            float gO = g_gi[(size_t)idxp * G4 + 384 + d];
            __syncthreads();  // A

            half2 ai[2] = {z, z}, af[2] = {z, z}, ag[2] = {z, z}, ao[2] = {z, z};
#pragma unroll
            for (int j = 0; j < 16; j++) {
                const uint4 xv = hh4[h4 + j];
                const uint4 wi = wS[j * G4 + d];
                const uint4 wf = wS[j * G4 + 128 + d];
                const uint4 wg = wS[j * G4 + 256 + d];
                const uint4 wo = wS[j * G4 + 384 + d];
                const int q = j & 1;
                ai[q] = __hfma2(as_h2(wi.x), as_h2(xv.x), ai[q]);
                ai[q] = __hfma2(as_h2(wi.y), as_h2(xv.y), ai[q]);
                ai[q] = __hfma2(as_h2(wi.z), as_h2(xv.z), ai[q]);
                ai[q] = __hfma2(as_h2(wi.w), as_h2(xv.w), ai[q]);
                af[q] = __hfma2(as_h2(wf.x), as_h2(xv.x), af[q]);
                af[q] = __hfma2(as_h2(wf.y), as_h2(xv.y), af[q]);
                af[q] = __hfma2(as_h2(wf.z), as_h2(xv.z), af[q]);
                af[q] = __hfma2(as_h2(wf.w), as_h2(xv.w), af[q]);
                ag[q] = __hfma2(as_h2(wg.x), as_h2(xv.x), ag[q]);
                ag[q] = __hfma2(as_h2(wg.y), as_h2(xv.y), ag[q]);
                ag[q] = __hfma2(as_h2(wg.z), as_h2(xv.z), ag[q]);
                ag[q] = __hfma2(as_h2(wg.w), as_h2(xv.w), ag[q]);
                ao[q] = __hfma2(as_h2(wo.x), as_h2(xv.x), ao[q]);
                ao[q] = __hfma2(as_h2(wo.y), as_h2(xv.y), ao[q]);
                ao[q] = __hfma2(as_h2(wo.z), as_h2(xv.z), ao[q]);
                ao[q] = __hfma2(as_h2(wo.w), as_h2(xv.w), ao[q]);
            }
            gI += h2sumf(ai[0]) + h2sumf(ai[1]);
            gF += h2sumf(af[0]) + h2sumf(af[1]);
            gG += h2sumf(ag[0]) + h2sumf(ag[1]);
            gO += h2sumf(ao[0]) + h2sumf(ao[1]);
            c = sigf(gF) * cin + sigf(gI) * ftanh(gG);
            h = sigf(gO) * ftanh(c);
            g_H[(size_t)idxp * DD + d] = h;
            g_C[(size_t)idxp * DD + d] = c;
            __syncthreads();  // B
        }
    }
}

// ---------------- Kernel F: out = sigmoid(H . pW + pb) -------------------------
__global__ __launch_bounds__(256) void kF(const float* __restrict__ pW,
                                          const float* __restrict__ pb,
                                          float* __restrict__ out) {
    const int gw = blockIdx.x * 8 + (threadIdx.x >> 5);
    const int lane = threadIdx.x & 31;
    const float4 hv = ((const float4*)(g_H + (size_t)gw * DD))[lane];
    const float4 pv = ((const float4*)pW)[lane];
    float v = hv.x * pv.x + hv.y * pv.y + hv.z * pv.z + hv.w * pv.w;
    v = warp_sum(v);
    if (lane == 0) out[gw] = sigf(v + pb[0]);
}

// ---------------- launch ----------------
extern "C" void kernel_launch(void* const* d_in, const int* in_sizes, int n_in,
                              void* d_out, int out_size) {
    const int* q = (const int*)d_in[0];
    const int* r = (const int*)d_in[1];
    const float* k_emb = (const float*)d_in[2];
    const float* Mk = (const float*)d_in[3];
    const float* Mv0 = (const float*)d_in[4];
    const float* fW = (const float*)d_in[5];
    const float* fb = (const float*)d_in[6];
    const float* aW = (const float*)d_in[7];
    const float* ab = (const float*)d_in[8];
    const float* eW = (const float*)d_in[9];
    const float* eb = (const float*)d_in[10];
    const float* addW = (const float*)d_in[11];
    const float* addb = (const float*)d_in[12];
    const float* Wih = (const float*)d_in[13];
    const float* Whh = (const float*)d_in[14];
    const float* bih = (const float*)d_in[15];
    const float* bhh = (const float*)d_in[16];
    const float* pW = (const float*)d_in[17];
    const float* pb = (const float*)d_in[18];
    float* out = (float*)d_out;

    cudaFuncSetAttribute(kScan, cudaFuncAttributeMaxDynamicSharedMemorySize, SC_SMEM);

    kA<<<256, 256>>>(q, r, k_emb, Mk, aW);
    kB<<<RR / 8, 256>>>();
    kScan<<<3 * NPAIR, 256, SC_SMEM>>>(fW, fb, aW, ab, eW, eb, addW, addb, Mv0,
                                       Wih, bih, bhh, Whh);
    kF<<<RR / 8, 256>>>(pW, pb, out);
}